// round 1
// baseline (speedup 1.0000x reference)
#include <cuda_runtime.h>
#include <math.h>

// Problem constants
#define BSZ 2
#define TSEQ 2048
#define DM   1024
#define HN   16
#define HDM  64
#define MTOT (BSZ*TSEQ)   // 4096

// Scratch (allocation-free rule: __device__ globals)
__device__ float g_Q [BSZ*HN*TSEQ*HDM];   // [B,H,T,hd], pre-scaled by 1/sqrt(hd)
__device__ float g_Kt[BSZ*HN*HDM*TSEQ];   // [B,H,hd,T]  (transposed K)
__device__ float g_V [BSZ*HN*TSEQ*HDM];   // [B,H,T,hd]
__device__ float g_O [MTOT*DM];           // [B*T, D] attention output

// ---------------------------------------------------------------------------
// Tiled NT SGEMM core: C = A @ W^T. A[M,1024] row-major, W[N,1024] row-major.
// 128x128 block tile, BK=8, 256 threads, 8x8 per-thread micro-tile.
// ---------------------------------------------------------------------------
__device__ __forceinline__ void gemm_tile_compute(
    const float* __restrict__ A, const float* __restrict__ W,
    int bm, int bn, float acc[8][8])
{
    __shared__ float As[8][128];
    __shared__ float Bs[8][128];
    const int tid  = threadIdx.x;
    const int lrow = tid >> 1;          // 0..127
    const int lcol = (tid & 1) << 2;    // 0 or 4
    const int tx   = tid & 15;
    const int ty   = tid >> 4;

    const float* Ag = A + (size_t)(bm * 128 + lrow) * 1024 + lcol;
    const float* Wg = W + (size_t)(bn * 128 + lrow) * 1024 + lcol;

#pragma unroll
    for (int i = 0; i < 8; i++)
#pragma unroll
        for (int j = 0; j < 8; j++) acc[i][j] = 0.f;

    for (int k0 = 0; k0 < 1024; k0 += 8) {
        float4 av = *(const float4*)(Ag + k0);
        float4 wv = *(const float4*)(Wg + k0);
        __syncthreads();
        As[lcol + 0][lrow] = av.x; As[lcol + 1][lrow] = av.y;
        As[lcol + 2][lrow] = av.z; As[lcol + 3][lrow] = av.w;
        Bs[lcol + 0][lrow] = wv.x; Bs[lcol + 1][lrow] = wv.y;
        Bs[lcol + 2][lrow] = wv.z; Bs[lcol + 3][lrow] = wv.w;
        __syncthreads();
#pragma unroll
        for (int k = 0; k < 8; k++) {
            float a[8], b[8];
            *(float4*)&a[0] = *(const float4*)&As[k][ty * 8];
            *(float4*)&a[4] = *(const float4*)&As[k][ty * 8 + 4];
            *(float4*)&b[0] = *(const float4*)&Bs[k][tx * 8];
            *(float4*)&b[4] = *(const float4*)&Bs[k][tx * 8 + 4];
#pragma unroll
            for (int i = 0; i < 8; i++)
#pragma unroll
                for (int j = 0; j < 8; j++) acc[i][j] += a[i] * b[j];
        }
    }
}

// ---------------------------------------------------------------------------
// Fused QKV projection. blockIdx.z selects Q(0)/K(1)/V(2).
// Q epilogue: scale by 1/sqrt(64), store [B,H,T,hd].
// K epilogue: store transposed [B,H,hd,T] (scalar scatter; paid once).
// V epilogue: store [B,H,T,hd].
// ---------------------------------------------------------------------------
__global__ void __launch_bounds__(256) qkv_gemm_kernel(
    const float* __restrict__ x, const float* __restrict__ wq,
    const float* __restrict__ wk, const float* __restrict__ wv)
{
    const int z = blockIdx.z;
    const float* W = (z == 0) ? wq : (z == 1) ? wk : wv;
    float acc[8][8];
    gemm_tile_compute(x, W, blockIdx.y, blockIdx.x, acc);

    const int tid = threadIdx.x;
    const int tx = tid & 15, ty = tid >> 4;
    const int m0 = blockIdx.y * 128 + ty * 8;
    const int n0 = blockIdx.x * 128 + tx * 8;

    if (z == 0) {
#pragma unroll
        for (int i = 0; i < 8; i++) {
            int m = m0 + i; int b = m / TSEQ, t = m % TSEQ;
#pragma unroll
            for (int jv = 0; jv < 2; jv++) {
                int n = n0 + jv * 4; int h = n >> 6, d = n & 63;
                float4 v = make_float4(acc[i][jv*4+0] * 0.125f, acc[i][jv*4+1] * 0.125f,
                                       acc[i][jv*4+2] * 0.125f, acc[i][jv*4+3] * 0.125f);
                *(float4*)&g_Q[((size_t)(b * HN + h) * TSEQ + t) * HDM + d] = v;
            }
        }
    } else if (z == 2) {
#pragma unroll
        for (int i = 0; i < 8; i++) {
            int m = m0 + i; int b = m / TSEQ, t = m % TSEQ;
#pragma unroll
            for (int jv = 0; jv < 2; jv++) {
                int n = n0 + jv * 4; int h = n >> 6, d = n & 63;
                float4 v = make_float4(acc[i][jv*4+0], acc[i][jv*4+1],
                                       acc[i][jv*4+2], acc[i][jv*4+3]);
                *(float4*)&g_V[((size_t)(b * HN + h) * TSEQ + t) * HDM + d] = v;
            }
        }
    } else {
#pragma unroll
        for (int i = 0; i < 8; i++) {
            int m = m0 + i; int b = m / TSEQ, t = m % TSEQ;
#pragma unroll
            for (int j = 0; j < 8; j++) {
                int n = n0 + j; int h = n >> 6, d = n & 63;
                g_Kt[((size_t)(b * HN + h) * HDM + d) * TSEQ + t] = acc[i][j];
            }
        }
    }
}

// ---------------------------------------------------------------------------
// Causal flash attention, fp32. BM=BN=64, 256 threads (16x16), 4x4 micro-tiles.
// Smem: Qs[m][d] (pre-scaled Q), KPs = K-tile [d][n] aliased with P-tile [m][k],
// Vs[k][d]. Exactly 48KB static.
// ---------------------------------------------------------------------------
__global__ void __launch_bounds__(256) flash_attn_kernel()
{
    __shared__ float Qs [64 * 64];
    __shared__ float KPs[64 * 64];
    __shared__ float Vs [64 * 64];

    const int tid = threadIdx.x;
    const int tx = tid & 15, ty = tid >> 4;
    const int qt = blockIdx.x;          // q tile: rows qt*64 .. +63
    const int bh = blockIdx.y;          // b*H + h

    const float* Qg  = g_Q  + (size_t)bh * TSEQ * HDM + (size_t)qt * 64 * HDM;
    const float* Ktg = g_Kt + (size_t)bh * HDM * TSEQ;
    const float* Vg  = g_V  + (size_t)bh * TSEQ * HDM;

    // Q tile: contiguous 16KB copy
#pragma unroll
    for (int it = 0; it < 4; it++) {
        int u = tid + it * 256;
        *(float4*)&Qs[u * 4] = *(const float4*)&Qg[u * 4];
    }

    float mi[4], li[4], o[4][4];
#pragma unroll
    for (int i = 0; i < 4; i++) {
        mi[i] = -INFINITY; li[i] = 0.f;
#pragma unroll
        for (int j = 0; j < 4; j++) o[i][j] = 0.f;
    }

    for (int kt = 0; kt <= qt; kt++) {
        __syncthreads();  // prior P/V reads complete before overwrite
        // K tile [d][n] from transposed K (coalesced rows), V tile contiguous
#pragma unroll
        for (int it = 0; it < 4; it++) {
            int u = tid + it * 256;          // float4 index in [64][16]
            int d = u >> 4, n4 = u & 15;
            *(float4*)&KPs[d * 64 + n4 * 4] =
                *(const float4*)&Ktg[(size_t)d * TSEQ + kt * 64 + n4 * 4];
            *(float4*)&Vs[u * 4] = *(const float4*)&Vg[(size_t)kt * 64 * HDM + u * 4];
        }
        __syncthreads();

        // S = Q * K^T  (Q already scaled)
        float s[4][4];
#pragma unroll
        for (int i = 0; i < 4; i++)
#pragma unroll
            for (int j = 0; j < 4; j++) s[i][j] = 0.f;
#pragma unroll 16
        for (int k = 0; k < 64; k++) {
            float a0 = Qs[(ty * 4 + 0) * 64 + k];
            float a1 = Qs[(ty * 4 + 1) * 64 + k];
            float a2 = Qs[(ty * 4 + 2) * 64 + k];
            float a3 = Qs[(ty * 4 + 3) * 64 + k];
            float4 bv = *(const float4*)&KPs[k * 64 + tx * 4];
            s[0][0] += a0 * bv.x; s[0][1] += a0 * bv.y; s[0][2] += a0 * bv.z; s[0][3] += a0 * bv.w;
            s[1][0] += a1 * bv.x; s[1][1] += a1 * bv.y; s[1][2] += a1 * bv.z; s[1][3] += a1 * bv.w;
            s[2][0] += a2 * bv.x; s[2][1] += a2 * bv.y; s[2][2] += a2 * bv.z; s[2][3] += a2 * bv.w;
            s[3][0] += a3 * bv.x; s[3][1] += a3 * bv.y; s[3][2] += a3 * bv.z; s[3][3] += a3 * bv.w;
        }

        if (kt == qt) {  // causal mask on diagonal tile
#pragma unroll
            for (int i = 0; i < 4; i++)
#pragma unroll
                for (int j = 0; j < 4; j++)
                    if (tx * 4 + j > ty * 4 + i) s[i][j] = -INFINITY;
        }

        // Online softmax (row groups = 16 consecutive lanes; xor 8/4/2/1 stays in-group)
        float pv[4][4];
#pragma unroll
        for (int i = 0; i < 4; i++) {
            float rm = fmaxf(fmaxf(s[i][0], s[i][1]), fmaxf(s[i][2], s[i][3]));
#pragma unroll
            for (int off = 8; off > 0; off >>= 1)
                rm = fmaxf(rm, __shfl_xor_sync(0xffffffffu, rm, off));
            float mnew  = fmaxf(mi[i], rm);
            float alpha = __expf(mi[i] - mnew);
            float rs = 0.f;
#pragma unroll
            for (int j = 0; j < 4; j++) {
                float p = __expf(s[i][j] - mnew);
                pv[i][j] = p; rs += p;
            }
#pragma unroll
            for (int off = 8; off > 0; off >>= 1)
                rs += __shfl_xor_sync(0xffffffffu, rs, off);
            li[i] = li[i] * alpha + rs;
            mi[i] = mnew;
#pragma unroll
            for (int j = 0; j < 4; j++) o[i][j] *= alpha;
        }

        __syncthreads();  // K-tile reads done; reuse KPs as P[m][k]
#pragma unroll
        for (int i = 0; i < 4; i++) {
            float4 v = make_float4(pv[i][0], pv[i][1], pv[i][2], pv[i][3]);
            *(float4*)&KPs[(ty * 4 + i) * 64 + tx * 4] = v;
        }
        __syncthreads();

        // O += P @ V
#pragma unroll 16
        for (int k = 0; k < 64; k++) {
            float a0 = KPs[(ty * 4 + 0) * 64 + k];
            float a1 = KPs[(ty * 4 + 1) * 64 + k];
            float a2 = KPs[(ty * 4 + 2) * 64 + k];
            float a3 = KPs[(ty * 4 + 3) * 64 + k];
            float4 bv = *(const float4*)&Vs[k * 64 + tx * 4];
            o[0][0] += a0 * bv.x; o[0][1] += a0 * bv.y; o[0][2] += a0 * bv.z; o[0][3] += a0 * bv.w;
            o[1][0] += a1 * bv.x; o[1][1] += a1 * bv.y; o[1][2] += a1 * bv.z; o[1][3] += a1 * bv.w;
            o[2][0] += a2 * bv.x; o[2][1] += a2 * bv.y; o[2][2] += a2 * bv.z; o[2][3] += a2 * bv.w;
            o[3][0] += a3 * bv.x; o[3][1] += a3 * bv.y; o[3][2] += a3 * bv.z; o[3][3] += a3 * bv.w;
        }
    }

    // Epilogue: O / l, store merged-head layout [B*T, D]
    const int b = bh >> 4, h = bh & 15;
#pragma unroll
    for (int i = 0; i < 4; i++) {
        int t = qt * 64 + ty * 4 + i;
        float inv = 1.f / li[i];
        float4 v = make_float4(o[i][0] * inv, o[i][1] * inv, o[i][2] * inv, o[i][3] * inv);
        *(float4*)&g_O[((size_t)(b * TSEQ + t)) * DM + h * 64 + tx * 4] = v;
    }
}

// ---------------------------------------------------------------------------
// Output projection: d_out = g_O @ wo^T
// ---------------------------------------------------------------------------
__global__ void __launch_bounds__(256) out_gemm_kernel(
    const float* __restrict__ wo, float* __restrict__ out)
{
    float acc[8][8];
    gemm_tile_compute(g_O, wo, blockIdx.y, blockIdx.x, acc);

    const int tid = threadIdx.x;
    const int tx = tid & 15, ty = tid >> 4;
    const int m0 = blockIdx.y * 128 + ty * 8;
    const int n0 = blockIdx.x * 128 + tx * 8;
#pragma unroll
    for (int i = 0; i < 8; i++) {
#pragma unroll
        for (int jv = 0; jv < 2; jv++) {
            float4 v = make_float4(acc[i][jv*4+0], acc[i][jv*4+1],
                                   acc[i][jv*4+2], acc[i][jv*4+3]);
            *(float4*)&out[(size_t)(m0 + i) * DM + n0 + jv * 4] = v;
        }
    }
}

// ---------------------------------------------------------------------------
extern "C" void kernel_launch(void* const* d_in, const int* in_sizes, int n_in,
                              void* d_out, int out_size)
{
    const float* x  = (const float*)d_in[0];
    const float* wq = (const float*)d_in[1];
    const float* wk = (const float*)d_in[2];
    const float* wv = (const float*)d_in[3];
    const float* wo = (const float*)d_in[4];

    qkv_gemm_kernel<<<dim3(DM / 128, MTOT / 128, 3), 256>>>(x, wq, wk, wv);
    flash_attn_kernel<<<dim3(TSEQ / 64, BSZ * HN), 256>>>();
    out_gemm_kernel<<<dim3(DM / 128, MTOT / 128), 256>>>(wo, (float*)d_out);
}

// round 5
// speedup vs baseline: 1.6748x; 1.6748x over previous
#include <cuda_runtime.h>
#include <math.h>
#include <cstdint>

// Problem constants
#define BSZ 2
#define TSEQ 2048
#define DM   1024
#define HN   16
#define HDM  64
#define MTOT (BSZ*TSEQ)   // 4096

// Scratch (allocation-free rule: __device__ globals)
__device__ float g_Q [BSZ*HN*TSEQ*HDM];   // [B,H,T,hd], pre-scaled by 1/sqrt(hd)
__device__ float g_Kt[BSZ*HN*HDM*TSEQ];   // [B,H,hd,T]  (transposed K)
__device__ float g_V [BSZ*HN*TSEQ*HDM];   // [B,H,T,hd]
__device__ float g_O [MTOT*DM];           // [B*T, D] attention output

// ---------------------------------------------------------------------------
// tf32 helpers (sm_80+ PTX; valid on compute_100)
// cvt.rna.tf32.f32 destination is a .b32 register -> "=r" constraint.
// ---------------------------------------------------------------------------
__device__ __forceinline__ float tf32r(float x) {
    uint32_t y;
    asm("cvt.rna.tf32.f32 %0, %1;" : "=r"(y) : "f"(x));
    return __uint_as_float(y);
}

__device__ __forceinline__ void mma_tf32(float c[4], uint32_t a0, uint32_t a1,
                                         uint32_t a2, uint32_t a3,
                                         uint32_t b0, uint32_t b1) {
    asm volatile(
        "mma.sync.aligned.m16n8k8.row.col.f32.tf32.tf32.f32 "
        "{%0,%1,%2,%3}, {%4,%5,%6,%7}, {%8,%9}, {%0,%1,%2,%3};"
        : "+f"(c[0]), "+f"(c[1]), "+f"(c[2]), "+f"(c[3])
        : "r"(a0), "r"(a1), "r"(a2), "r"(a3), "r"(b0), "r"(b1));
}

// ---------------------------------------------------------------------------
// mma.sync tf32 GEMM mainloop: acc(64x32 per warp) for C = A @ W^T tile.
// A[M,1024], W[N,1024] row-major fp32. 256 threads = 8 warps (2x4).
// BK=16, double-buffered smem [128][20] (pad 20 -> conflict-free fragments).
// Values stored in smem are already tf32-rounded.
// ---------------------------------------------------------------------------
#define PADK 20

__device__ __forceinline__ void gemm_mma_mainloop(
    const float* __restrict__ A, const float* __restrict__ W,
    int m0, int n0, float acc[4][4][4])
{
    __shared__ float As[2][128 * PADK];
    __shared__ float Ws[2][128 * PADK];

    const int tid  = threadIdx.x;
    const int lane = tid & 31, wid = tid >> 5;
    const int wm = wid & 1, wn = wid >> 1;
    const int g = lane >> 2, t = lane & 3;

    // Loader mapping: thread handles float4 rows (tid>>2) and (tid>>2)+64
    const int lrow = tid >> 2, lc4 = tid & 3;
    const float4* Ag0 = (const float4*)A + (size_t)(m0 + lrow) * 256 + lc4;
    const float4* Ag1 = Ag0 + (size_t)64 * 256;
    const float4* Wg0 = (const float4*)W + (size_t)(n0 + lrow) * 256 + lc4;
    const float4* Wg1 = Wg0 + (size_t)64 * 256;
    float* sA0 = &As[0][lrow * PADK + lc4 * 4];
    float* sA1 = &As[0][(lrow + 64) * PADK + lc4 * 4];
    float* sW0 = &Ws[0][lrow * PADK + lc4 * 4];
    float* sW1 = &Ws[0][(lrow + 64) * PADK + lc4 * 4];

#pragma unroll
    for (int mi = 0; mi < 4; mi++)
#pragma unroll
        for (int nj = 0; nj < 4; nj++)
#pragma unroll
            for (int e = 0; e < 4; e++) acc[mi][nj][e] = 0.f;

    float4 pa0 = Ag0[0], pa1 = Ag1[0], pw0 = Wg0[0], pw1 = Wg1[0];

    // store (with tf32 rounding) into buffer s
    auto sts = [&](int s) {
        const int o = s * 128 * PADK;
        *(float4*)(sA0 + o) = make_float4(tf32r(pa0.x), tf32r(pa0.y), tf32r(pa0.z), tf32r(pa0.w));
        *(float4*)(sA1 + o) = make_float4(tf32r(pa1.x), tf32r(pa1.y), tf32r(pa1.z), tf32r(pa1.w));
        *(float4*)(sW0 + o) = make_float4(tf32r(pw0.x), tf32r(pw0.y), tf32r(pw0.z), tf32r(pw0.w));
        *(float4*)(sW1 + o) = make_float4(tf32r(pw1.x), tf32r(pw1.y), tf32r(pw1.z), tf32r(pw1.w));
    };

    sts(0);
    __syncthreads();

    const int ra = wm * 64 + g;       // A row base for this thread
    const int cb = wn * 32 + g;       // B (W) row base

    for (int ch = 0; ch < 64; ch++) {
        const int s = ch & 1;
        if (ch < 63) {
            const size_t ko = (size_t)(ch + 1) * 4;   // float4 offset
            pa0 = Ag0[ko]; pa1 = Ag1[ko];
            pw0 = Wg0[ko]; pw1 = Wg1[ko];
        }
        const float* as = As[s];
        const float* ws = Ws[s];
#pragma unroll
        for (int ks = 0; ks < 16; ks += 8) {
            uint32_t af[4][4], bf[4][2];
#pragma unroll
            for (int mi = 0; mi < 4; mi++) {
                const int r = ra + mi * 16;
                af[mi][0] = __float_as_uint(as[r * PADK + ks + t]);
                af[mi][1] = __float_as_uint(as[(r + 8) * PADK + ks + t]);
                af[mi][2] = __float_as_uint(as[r * PADK + ks + t + 4]);
                af[mi][3] = __float_as_uint(as[(r + 8) * PADK + ks + t + 4]);
            }
#pragma unroll
            for (int nj = 0; nj < 4; nj++) {
                const int c = cb + nj * 8;
                bf[nj][0] = __float_as_uint(ws[c * PADK + ks + t]);
                bf[nj][1] = __float_as_uint(ws[c * PADK + ks + t + 4]);
            }
#pragma unroll
            for (int mi = 0; mi < 4; mi++)
#pragma unroll
                for (int nj = 0; nj < 4; nj++)
                    mma_tf32(acc[mi][nj], af[mi][0], af[mi][1], af[mi][2], af[mi][3],
                             bf[nj][0], bf[nj][1]);
        }
        if (ch < 63) {
            sts(s ^ 1);
            __syncthreads();
        }
    }
}

// ---------------------------------------------------------------------------
// Fused QKV projection. blockIdx.z: 0=Q (scaled, [B,H,T,hd]), 1=K^T, 2=V
// ---------------------------------------------------------------------------
__global__ void __launch_bounds__(256) qkv_mma_kernel(
    const float* __restrict__ x, const float* __restrict__ wq,
    const float* __restrict__ wk, const float* __restrict__ wv)
{
    const int z = blockIdx.z;
    const float* W = (z == 0) ? wq : (z == 1) ? wk : wv;
    const int m0 = blockIdx.y * 128, n0 = blockIdx.x * 128;

    float acc[4][4][4];
    gemm_mma_mainloop(x, W, m0, n0, acc);

    const int tid = threadIdx.x;
    const int lane = tid & 31, wid = tid >> 5;
    const int wm = wid & 1, wn = wid >> 1;
    const int g = lane >> 2, t = lane & 3;

#pragma unroll
    for (int mi = 0; mi < 4; mi++) {
#pragma unroll
        for (int half = 0; half < 2; half++) {
            const int m = m0 + wm * 64 + mi * 16 + g + half * 8;
            const int bb = m >> 11, tt = m & 2047;
#pragma unroll
            for (int nj = 0; nj < 4; nj++) {
                const int n = n0 + wn * 32 + nj * 8 + t * 2;
                const int h = n >> 6, d = n & 63;
                float v0 = acc[mi][nj][half * 2 + 0];
                float v1 = acc[mi][nj][half * 2 + 1];
                if (z == 0) {
                    float2 v = make_float2(v0 * 0.125f, v1 * 0.125f);
                    *(float2*)&g_Q[((size_t)(bb * HN + h) * TSEQ + tt) * HDM + d] = v;
                } else if (z == 2) {
                    float2 v = make_float2(v0, v1);
                    *(float2*)&g_V[((size_t)(bb * HN + h) * TSEQ + tt) * HDM + d] = v;
                } else {
                    g_Kt[((size_t)(bb * HN + h) * HDM + d)     * TSEQ + tt] = v0;
                    g_Kt[((size_t)(bb * HN + h) * HDM + d + 1) * TSEQ + tt] = v1;
                }
            }
        }
    }
}

// ---------------------------------------------------------------------------
// Output projection: d_out = g_O @ wo^T
// ---------------------------------------------------------------------------
__global__ void __launch_bounds__(256) out_mma_kernel(
    const float* __restrict__ wo, float* __restrict__ out)
{
    const int m0 = blockIdx.y * 128, n0 = blockIdx.x * 128;

    float acc[4][4][4];
    gemm_mma_mainloop(g_O, wo, m0, n0, acc);

    const int tid = threadIdx.x;
    const int lane = tid & 31, wid = tid >> 5;
    const int wm = wid & 1, wn = wid >> 1;
    const int g = lane >> 2, t = lane & 3;

#pragma unroll
    for (int mi = 0; mi < 4; mi++) {
#pragma unroll
        for (int half = 0; half < 2; half++) {
            const int m = m0 + wm * 64 + mi * 16 + g + half * 8;
#pragma unroll
            for (int nj = 0; nj < 4; nj++) {
                const int n = n0 + wn * 32 + nj * 8 + t * 2;
                float2 v = make_float2(acc[mi][nj][half * 2 + 0],
                                       acc[mi][nj][half * 2 + 1]);
                *(float2*)&out[(size_t)m * DM + n] = v;
            }
        }
    }
}

// ---------------------------------------------------------------------------
// Causal flash attention, fp32 (unchanged — proven correct in round 1).
// ---------------------------------------------------------------------------
__global__ void __launch_bounds__(256) flash_attn_kernel()
{
    __shared__ float Qs [64 * 64];
    __shared__ float KPs[64 * 64];
    __shared__ float Vs [64 * 64];

    const int tid = threadIdx.x;
    const int tx = tid & 15, ty = tid >> 4;
    const int qt = blockIdx.x;
    const int bh = blockIdx.y;

    const float* Qg  = g_Q  + (size_t)bh * TSEQ * HDM + (size_t)qt * 64 * HDM;
    const float* Ktg = g_Kt + (size_t)bh * HDM * TSEQ;
    const float* Vg  = g_V  + (size_t)bh * TSEQ * HDM;

#pragma unroll
    for (int it = 0; it < 4; it++) {
        int u = tid + it * 256;
        *(float4*)&Qs[u * 4] = *(const float4*)&Qg[u * 4];
    }

    float mi[4], li[4], o[4][4];
#pragma unroll
    for (int i = 0; i < 4; i++) {
        mi[i] = -INFINITY; li[i] = 0.f;
#pragma unroll
        for (int j = 0; j < 4; j++) o[i][j] = 0.f;
    }

    for (int kt = 0; kt <= qt; kt++) {
        __syncthreads();
#pragma unroll
        for (int it = 0; it < 4; it++) {
            int u = tid + it * 256;
            int d = u >> 4, n4 = u & 15;
            *(float4*)&KPs[d * 64 + n4 * 4] =
                *(const float4*)&Ktg[(size_t)d * TSEQ + kt * 64 + n4 * 4];
            *(float4*)&Vs[u * 4] = *(const float4*)&Vg[(size_t)kt * 64 * HDM + u * 4];
        }
        __syncthreads();

        float s[4][4];
#pragma unroll
        for (int i = 0; i < 4; i++)
#pragma unroll
            for (int j = 0; j < 4; j++) s[i][j] = 0.f;
#pragma unroll 16
        for (int k = 0; k < 64; k++) {
            float a0 = Qs[(ty * 4 + 0) * 64 + k];
            float a1 = Qs[(ty * 4 + 1) * 64 + k];
            float a2 = Qs[(ty * 4 + 2) * 64 + k];
            float a3 = Qs[(ty * 4 + 3) * 64 + k];
            float4 bv = *(const float4*)&KPs[k * 64 + tx * 4];
            s[0][0] += a0 * bv.x; s[0][1] += a0 * bv.y; s[0][2] += a0 * bv.z; s[0][3] += a0 * bv.w;
            s[1][0] += a1 * bv.x; s[1][1] += a1 * bv.y; s[1][2] += a1 * bv.z; s[1][3] += a1 * bv.w;
            s[2][0] += a2 * bv.x; s[2][1] += a2 * bv.y; s[2][2] += a2 * bv.z; s[2][3] += a2 * bv.w;
            s[3][0] += a3 * bv.x; s[3][1] += a3 * bv.y; s[3][2] += a3 * bv.z; s[3][3] += a3 * bv.w;
        }

        if (kt == qt) {
#pragma unroll
            for (int i = 0; i < 4; i++)
#pragma unroll
                for (int j = 0; j < 4; j++)
                    if (tx * 4 + j > ty * 4 + i) s[i][j] = -INFINITY;
        }

        float pv[4][4];
#pragma unroll
        for (int i = 0; i < 4; i++) {
            float rm = fmaxf(fmaxf(s[i][0], s[i][1]), fmaxf(s[i][2], s[i][3]));
#pragma unroll
            for (int off = 8; off > 0; off >>= 1)
                rm = fmaxf(rm, __shfl_xor_sync(0xffffffffu, rm, off));
            float mnew  = fmaxf(mi[i], rm);
            float alpha = __expf(mi[i] - mnew);
            float rs = 0.f;
#pragma unroll
            for (int j = 0; j < 4; j++) {
                float p = __expf(s[i][j] - mnew);
                pv[i][j] = p; rs += p;
            }
#pragma unroll
            for (int off = 8; off > 0; off >>= 1)
                rs += __shfl_xor_sync(0xffffffffu, rs, off);
            li[i] = li[i] * alpha + rs;
            mi[i] = mnew;
#pragma unroll
            for (int j = 0; j < 4; j++) o[i][j] *= alpha;
        }

        __syncthreads();
#pragma unroll
        for (int i = 0; i < 4; i++) {
            float4 v = make_float4(pv[i][0], pv[i][1], pv[i][2], pv[i][3]);
            *(float4*)&KPs[(ty * 4 + i) * 64 + tx * 4] = v;
        }
        __syncthreads();

#pragma unroll 16
        for (int k = 0; k < 64; k++) {
            float a0 = KPs[(ty * 4 + 0) * 64 + k];
            float a1 = KPs[(ty * 4 + 1) * 64 + k];
            float a2 = KPs[(ty * 4 + 2) * 64 + k];
            float a3 = KPs[(ty * 4 + 3) * 64 + k];
            float4 bv = *(const float4*)&Vs[k * 64 + tx * 4];
            o[0][0] += a0 * bv.x; o[0][1] += a0 * bv.y; o[0][2] += a0 * bv.z; o[0][3] += a0 * bv.w;
            o[1][0] += a1 * bv.x; o[1][1] += a1 * bv.y; o[1][2] += a1 * bv.z; o[1][3] += a1 * bv.w;
            o[2][0] += a2 * bv.x; o[2][1] += a2 * bv.y; o[2][2] += a2 * bv.z; o[2][3] += a2 * bv.w;
            o[3][0] += a3 * bv.x; o[3][1] += a3 * bv.y; o[3][2] += a3 * bv.z; o[3][3] += a3 * bv.w;
        }
    }

    const int b = bh >> 4, h = bh & 15;
#pragma unroll
    for (int i = 0; i < 4; i++) {
        int t = qt * 64 + ty * 4 + i;
        float inv = 1.f / li[i];
        float4 v = make_float4(o[i][0] * inv, o[i][1] * inv, o[i][2] * inv, o[i][3] * inv);
        *(float4*)&g_O[((size_t)(b * TSEQ + t)) * DM + h * 64 + tx * 4] = v;
    }
}

// ---------------------------------------------------------------------------
extern "C" void kernel_launch(void* const* d_in, const int* in_sizes, int n_in,
                              void* d_out, int out_size)
{
    const float* x  = (const float*)d_in[0];
    const float* wq = (const float*)d_in[1];
    const float* wk = (const float*)d_in[2];
    const float* wv = (const float*)d_in[3];
    const float* wo = (const float*)d_in[4];

    qkv_mma_kernel<<<dim3(DM / 128, MTOT / 128, 3), 256>>>(x, wq, wk, wv);
    flash_attn_kernel<<<dim3(TSEQ / 64, BSZ * HN), 256>>>();
    out_mma_kernel<<<dim3(DM / 128, MTOT / 128), 256>>>(wo, (float*)d_out);
}

// round 7
// speedup vs baseline: 2.6554x; 1.5855x over previous
#include <cuda_runtime.h>
#include <math.h>
#include <cstdint>

// Problem constants
#define BSZ 2
#define TSEQ 2048
#define DM   1024
#define HN   16
#define HDM  64
#define MTOT (BSZ*TSEQ)   // 4096

// Scratch (allocation-free rule: __device__ globals)
__device__ float g_Q [BSZ*HN*TSEQ*HDM];   // [B,H,T,hd], pre-scaled by 1/sqrt(hd)
__device__ float g_K [BSZ*HN*TSEQ*HDM];   // [B,H,T,hd]  (natural K)
__device__ float g_Vt[BSZ*HN*HDM*TSEQ];   // [B,H,hd,T]  (transposed V)
__device__ float g_O [MTOT*DM];           // [B*T, D] attention output

// ---------------------------------------------------------------------------
// tf32 helpers (sm_80+ PTX; valid on compute_100)
// ---------------------------------------------------------------------------
__device__ __forceinline__ float tf32r(float x) {
    uint32_t y;
    asm("cvt.rna.tf32.f32 %0, %1;" : "=r"(y) : "f"(x));
    return __uint_as_float(y);
}
__device__ __forceinline__ float4 tf4(float4 v) {
    v.x = tf32r(v.x); v.y = tf32r(v.y); v.z = tf32r(v.z); v.w = tf32r(v.w);
    return v;
}

__device__ __forceinline__ void mma_tf32(float c[4], uint32_t a0, uint32_t a1,
                                         uint32_t a2, uint32_t a3,
                                         uint32_t b0, uint32_t b1) {
    asm volatile(
        "mma.sync.aligned.m16n8k8.row.col.f32.tf32.tf32.f32 "
        "{%0,%1,%2,%3}, {%4,%5,%6,%7}, {%8,%9}, {%0,%1,%2,%3};"
        : "+f"(c[0]), "+f"(c[1]), "+f"(c[2]), "+f"(c[3])
        : "r"(a0), "r"(a1), "r"(a2), "r"(a3), "r"(b0), "r"(b1));
}

// ---------------------------------------------------------------------------
// mma.sync tf32 GEMM mainloop (unchanged from passing round 5 kernel)
// ---------------------------------------------------------------------------
#define PADK 20

__device__ __forceinline__ void gemm_mma_mainloop(
    const float* __restrict__ A, const float* __restrict__ W,
    int m0, int n0, float acc[4][4][4])
{
    __shared__ float As[2][128 * PADK];
    __shared__ float Ws[2][128 * PADK];

    const int tid  = threadIdx.x;
    const int lane = tid & 31, wid = tid >> 5;
    const int wm = wid & 1, wn = wid >> 1;
    const int g = lane >> 2, t = lane & 3;

    const int lrow = tid >> 2, lc4 = tid & 3;
    const float4* Ag0 = (const float4*)A + (size_t)(m0 + lrow) * 256 + lc4;
    const float4* Ag1 = Ag0 + (size_t)64 * 256;
    const float4* Wg0 = (const float4*)W + (size_t)(n0 + lrow) * 256 + lc4;
    const float4* Wg1 = Wg0 + (size_t)64 * 256;
    float* sA0 = &As[0][lrow * PADK + lc4 * 4];
    float* sA1 = &As[0][(lrow + 64) * PADK + lc4 * 4];
    float* sW0 = &Ws[0][lrow * PADK + lc4 * 4];
    float* sW1 = &Ws[0][(lrow + 64) * PADK + lc4 * 4];

#pragma unroll
    for (int mi = 0; mi < 4; mi++)
#pragma unroll
        for (int nj = 0; nj < 4; nj++)
#pragma unroll
            for (int e = 0; e < 4; e++) acc[mi][nj][e] = 0.f;

    float4 pa0 = Ag0[0], pa1 = Ag1[0], pw0 = Wg0[0], pw1 = Wg1[0];

    auto sts = [&](int s) {
        const int o = s * 128 * PADK;
        *(float4*)(sA0 + o) = tf4(pa0);
        *(float4*)(sA1 + o) = tf4(pa1);
        *(float4*)(sW0 + o) = tf4(pw0);
        *(float4*)(sW1 + o) = tf4(pw1);
    };

    sts(0);
    __syncthreads();

    const int ra = wm * 64 + g;
    const int cb = wn * 32 + g;

    for (int ch = 0; ch < 64; ch++) {
        const int s = ch & 1;
        if (ch < 63) {
            const size_t ko = (size_t)(ch + 1) * 4;
            pa0 = Ag0[ko]; pa1 = Ag1[ko];
            pw0 = Wg0[ko]; pw1 = Wg1[ko];
        }
        const float* as = As[s];
        const float* ws = Ws[s];
#pragma unroll
        for (int ks = 0; ks < 16; ks += 8) {
            uint32_t af[4][4], bf[4][2];
#pragma unroll
            for (int mi = 0; mi < 4; mi++) {
                const int r = ra + mi * 16;
                af[mi][0] = __float_as_uint(as[r * PADK + ks + t]);
                af[mi][1] = __float_as_uint(as[(r + 8) * PADK + ks + t]);
                af[mi][2] = __float_as_uint(as[r * PADK + ks + t + 4]);
                af[mi][3] = __float_as_uint(as[(r + 8) * PADK + ks + t + 4]);
            }
#pragma unroll
            for (int nj = 0; nj < 4; nj++) {
                const int c = cb + nj * 8;
                bf[nj][0] = __float_as_uint(ws[c * PADK + ks + t]);
                bf[nj][1] = __float_as_uint(ws[c * PADK + ks + t + 4]);
            }
#pragma unroll
            for (int mi = 0; mi < 4; mi++)
#pragma unroll
                for (int nj = 0; nj < 4; nj++)
                    mma_tf32(acc[mi][nj], af[mi][0], af[mi][1], af[mi][2], af[mi][3],
                             bf[nj][0], bf[nj][1]);
        }
        if (ch < 63) {
            sts(s ^ 1);
            __syncthreads();
        }
    }
}

// ---------------------------------------------------------------------------
// Fused QKV projection. z: 0=Q (scaled, [B,H,T,hd]), 1=K natural, 2=V transposed
// ---------------------------------------------------------------------------
__global__ void __launch_bounds__(256) qkv_mma_kernel(
    const float* __restrict__ x, const float* __restrict__ wq,
    const float* __restrict__ wk, const float* __restrict__ wv)
{
    const int z = blockIdx.z;
    const float* W = (z == 0) ? wq : (z == 1) ? wk : wv;
    const int m0 = blockIdx.y * 128, n0 = blockIdx.x * 128;

    float acc[4][4][4];
    gemm_mma_mainloop(x, W, m0, n0, acc);

    const int tid = threadIdx.x;
    const int lane = tid & 31, wid = tid >> 5;
    const int wm = wid & 1, wn = wid >> 1;
    const int g = lane >> 2, t = lane & 3;

#pragma unroll
    for (int mi = 0; mi < 4; mi++) {
#pragma unroll
        for (int half = 0; half < 2; half++) {
            const int m = m0 + wm * 64 + mi * 16 + g + half * 8;
            const int bb = m >> 11, tt = m & 2047;
#pragma unroll
            for (int nj = 0; nj < 4; nj++) {
                const int n = n0 + wn * 32 + nj * 8 + t * 2;
                const int h = n >> 6, d = n & 63;
                float v0 = acc[mi][nj][half * 2 + 0];
                float v1 = acc[mi][nj][half * 2 + 1];
                if (z == 0) {
                    float2 v = make_float2(v0 * 0.125f, v1 * 0.125f);
                    *(float2*)&g_Q[((size_t)(bb * HN + h) * TSEQ + tt) * HDM + d] = v;
                } else if (z == 1) {
                    float2 v = make_float2(v0, v1);
                    *(float2*)&g_K[((size_t)(bb * HN + h) * TSEQ + tt) * HDM + d] = v;
                } else {
                    g_Vt[((size_t)(bb * HN + h) * HDM + d)     * TSEQ + tt] = v0;
                    g_Vt[((size_t)(bb * HN + h) * HDM + d + 1) * TSEQ + tt] = v1;
                }
            }
        }
    }
}

// ---------------------------------------------------------------------------
// Output projection: d_out = g_O @ wo^T
// ---------------------------------------------------------------------------
__global__ void __launch_bounds__(256) out_mma_kernel(
    const float* __restrict__ wo, float* __restrict__ out)
{
    const int m0 = blockIdx.y * 128, n0 = blockIdx.x * 128;

    float acc[4][4][4];
    gemm_mma_mainloop(g_O, wo, m0, n0, acc);

    const int tid = threadIdx.x;
    const int lane = tid & 31, wid = tid >> 5;
    const int wm = wid & 1, wn = wid >> 1;
    const int g = lane >> 2, t = lane & 3;

#pragma unroll
    for (int mi = 0; mi < 4; mi++) {
#pragma unroll
        for (int half = 0; half < 2; half++) {
            const int m = m0 + wm * 64 + mi * 16 + g + half * 8;
#pragma unroll
            for (int nj = 0; nj < 4; nj++) {
                const int n = n0 + wn * 32 + nj * 8 + t * 2;
                float2 v = make_float2(acc[mi][nj][half * 2 + 0],
                                       acc[mi][nj][half * 2 + 1]);
                *(float2*)&out[(size_t)m * DM + n] = v;
            }
        }
    }
}

// ---------------------------------------------------------------------------
// Causal flash attention on mma.sync tf32.
// BM=128 q-rows/CTA, BN=64 kv per iter, 256 threads = 8 warps, each warp owns
// 16 full rows (warp-local softmax). Q/K/V/P all tf32-rounded in smem.
// Smem: Qs[128][68], Ks[64][68], Vt[64][68], Ps[128][68] = 104448 B dynamic.
// ---------------------------------------------------------------------------
#define FPAD 68
#define FLASH_SMEM (384 * FPAD * 4)

__global__ void __launch_bounds__(256) flash_mma_kernel()
{
    extern __shared__ float fs[];
    float* Qs = fs;                    // [128][FPAD]
    float* Ks = fs + 128 * FPAD;       // [64][FPAD]
    float* Vt = Ks + 64 * FPAD;        // [64][FPAD]
    float* Ps = Vt + 64 * FPAD;        // [128][FPAD]

    const int tid = threadIdx.x, lane = tid & 31, w = tid >> 5;
    const int g = lane >> 2, t = lane & 3;
    const int qt = gridDim.x - 1 - blockIdx.x;   // heavy tiles first
    const int bh = blockIdx.y;
    const int q0 = qt * 128;
    const int rm = w * 16;

    const float* Qg = g_Q  + (size_t)bh * TSEQ * HDM + (size_t)q0 * HDM;
    const float* Kg = g_K  + (size_t)bh * TSEQ * HDM;
    const float* Vg = g_Vt + (size_t)bh * HDM * TSEQ;

    // Q tile (tf32-rounded)
#pragma unroll
    for (int it = 0; it < 8; it++) {
        int u = tid + it * 256, r = u >> 4, c = u & 15;
        *(float4*)&Qs[r * FPAD + c * 4] = tf4(*(const float4*)&Qg[(size_t)r * HDM + c * 4]);
    }

    float mi[2] = {-INFINITY, -INFINITY}, li[2] = {0.f, 0.f};
    float accO[8][4];
#pragma unroll
    for (int nj = 0; nj < 8; nj++)
#pragma unroll
        for (int e = 0; e < 4; e++) accO[nj][e] = 0.f;

    const int n_kt = 2 * (qt + 1);
    for (int kt = 0; kt < n_kt; kt++) {
        __syncthreads();   // prior-iter K/V reads complete
#pragma unroll
        for (int it = 0; it < 4; it++) {
            int u = tid + it * 256, r = u >> 4, c = u & 15;
            *(float4*)&Ks[r * FPAD + c * 4] =
                tf4(*(const float4*)&Kg[(size_t)(kt * 64 + r) * HDM + c * 4]);
            *(float4*)&Vt[r * FPAD + c * 4] =
                tf4(*(const float4*)&Vg[(size_t)r * TSEQ + kt * 64 + c * 4]);
        }
        __syncthreads();

        // S = Q @ K^T  (Q pre-scaled)
        float s[8][4];
#pragma unroll
        for (int nj = 0; nj < 8; nj++)
#pragma unroll
            for (int e = 0; e < 4; e++) s[nj][e] = 0.f;
#pragma unroll
        for (int ks = 0; ks < 8; ks++) {
            const int kk = ks * 8;
            uint32_t a0 = __float_as_uint(Qs[(rm + g) * FPAD + kk + t]);
            uint32_t a1 = __float_as_uint(Qs[(rm + g + 8) * FPAD + kk + t]);
            uint32_t a2 = __float_as_uint(Qs[(rm + g) * FPAD + kk + t + 4]);
            uint32_t a3 = __float_as_uint(Qs[(rm + g + 8) * FPAD + kk + t + 4]);
#pragma unroll
            for (int nj = 0; nj < 8; nj++) {
                uint32_t b0 = __float_as_uint(Ks[(nj * 8 + g) * FPAD + kk + t]);
                uint32_t b1 = __float_as_uint(Ks[(nj * 8 + g) * FPAD + kk + t + 4]);
                mma_tf32(s[nj], a0, a1, a2, a3, b0, b1);
            }
        }

        if (kt >= 2 * qt) {  // causal mask (only the two diagonal-band tiles)
            const int r0 = q0 + rm + g, r1 = r0 + 8;
#pragma unroll
            for (int nj = 0; nj < 8; nj++) {
                const int col = kt * 64 + nj * 8 + 2 * t;
                if (col     > r0) s[nj][0] = -INFINITY;
                if (col + 1 > r0) s[nj][1] = -INFINITY;
                if (col     > r1) s[nj][2] = -INFINITY;
                if (col + 1 > r1) s[nj][3] = -INFINITY;
            }
        }

        // Online softmax per row-half; P -> smem (tf32-rounded), same-warp rows
#pragma unroll
        for (int h = 0; h < 2; h++) {
            float vm = -INFINITY;
#pragma unroll
            for (int nj = 0; nj < 8; nj++)
                vm = fmaxf(vm, fmaxf(s[nj][2 * h], s[nj][2 * h + 1]));
            vm = fmaxf(vm, __shfl_xor_sync(0xffffffffu, vm, 1));
            vm = fmaxf(vm, __shfl_xor_sync(0xffffffffu, vm, 2));
            const float mnew = fmaxf(mi[h], vm);
            const float alpha = __expf(mi[h] - mnew);
            float rs = 0.f;
            const int prow = (rm + g + 8 * h) * FPAD + 2 * t;
#pragma unroll
            for (int nj = 0; nj < 8; nj++) {
                float p0 = __expf(s[nj][2 * h]     - mnew);
                float p1 = __expf(s[nj][2 * h + 1] - mnew);
                rs += p0 + p1;
                *(float2*)&Ps[prow + nj * 8] = make_float2(tf32r(p0), tf32r(p1));
            }
            rs += __shfl_xor_sync(0xffffffffu, rs, 1);
            rs += __shfl_xor_sync(0xffffffffu, rs, 2);
            li[h] = li[h] * alpha + rs;
            mi[h] = mnew;
#pragma unroll
            for (int nj = 0; nj < 8; nj++) {
                accO[nj][2 * h]     *= alpha;
                accO[nj][2 * h + 1] *= alpha;
            }
        }
        __syncwarp();

        // O += P @ V   (B operand = transposed V: Vt[d][token])
#pragma unroll
        for (int ks = 0; ks < 8; ks++) {
            const int kk = ks * 8;
            uint32_t a0 = __float_as_uint(Ps[(rm + g) * FPAD + kk + t]);
            uint32_t a1 = __float_as_uint(Ps[(rm + g + 8) * FPAD + kk + t]);
            uint32_t a2 = __float_as_uint(Ps[(rm + g) * FPAD + kk + t + 4]);
            uint32_t a3 = __float_as_uint(Ps[(rm + g + 8) * FPAD + kk + t + 4]);
#pragma unroll
            for (int nj = 0; nj < 8; nj++) {
                uint32_t b0 = __float_as_uint(Vt[(nj * 8 + g) * FPAD + kk + t]);
                uint32_t b1 = __float_as_uint(Vt[(nj * 8 + g) * FPAD + kk + t + 4]);
                mma_tf32(accO[nj], a0, a1, a2, a3, b0, b1);
            }
        }
    }

    // Epilogue: O / l into merged-head layout [B*T, D]
    const int b = bh >> 4, hh = bh & 15;
    const float inv0 = 1.f / li[0], inv1 = 1.f / li[1];
    const int r0 = q0 + rm + g;
#pragma unroll
    for (int nj = 0; nj < 8; nj++) {
        const int col = hh * 64 + nj * 8 + 2 * t;
        *(float2*)&g_O[(size_t)(b * TSEQ + r0) * DM + col] =
            make_float2(accO[nj][0] * inv0, accO[nj][1] * inv0);
        *(float2*)&g_O[(size_t)(b * TSEQ + r0 + 8) * DM + col] =
            make_float2(accO[nj][2] * inv1, accO[nj][3] * inv1);
    }
}

// ---------------------------------------------------------------------------
extern "C" void kernel_launch(void* const* d_in, const int* in_sizes, int n_in,
                              void* d_out, int out_size)
{
    const float* x  = (const float*)d_in[0];
    const float* wq = (const float*)d_in[1];
    const float* wk = (const float*)d_in[2];
    const float* wv = (const float*)d_in[3];
    const float* wo = (const float*)d_in[4];

    cudaFuncSetAttribute(flash_mma_kernel,
                         cudaFuncAttributeMaxDynamicSharedMemorySize, FLASH_SMEM);

    qkv_mma_kernel<<<dim3(DM / 128, MTOT / 128, 3), 256>>>(x, wq, wk, wv);
    flash_mma_kernel<<<dim3(TSEQ / 128, BSZ * HN), 256, FLASH_SMEM>>>();
    out_mma_kernel<<<dim3(DM / 128, MTOT / 128), 256>>>(wo, (float*)d_out);
}

// round 8
// speedup vs baseline: 4.1073x; 1.5468x over previous
#include <cuda_runtime.h>
#include <cuda_fp16.h>
#include <math.h>
#include <cstdint>

// Problem constants
#define BSZ 2
#define TSEQ 2048
#define DM   1024
#define HN   16
#define HDM  64
#define MTOT (BSZ*TSEQ)   // 4096

// Scratch (allocation-free rule: __device__ globals)
__device__ float g_Q [BSZ*HN*TSEQ*HDM];   // [B,H,T,hd], pre-scaled by 1/sqrt(hd)
__device__ float g_K [BSZ*HN*TSEQ*HDM];   // [B,H,T,hd]  (natural K)
__device__ float g_Vt[BSZ*HN*HDM*TSEQ];   // [B,H,hd,T]  (transposed V)
__device__ float g_O [MTOT*DM];           // [B*T, D] attention output

// ---------------------------------------------------------------------------
// fp16 helpers. pk(lo,hi): half2 with lo in low 16 bits (k-even element).
// ---------------------------------------------------------------------------
__device__ __forceinline__ uint32_t pk(float lo, float hi) {
    __half2 h = __floats2half2_rn(lo, hi);
    return *(uint32_t*)&h;
}

// mma.sync m16n8k16 fp16 inputs, fp32 accum. Fragment positions match the
// m16n8k8 tf32 layout with k packed in half2 pairs; C layout identical.
__device__ __forceinline__ void mma_f16(float c[4], uint32_t a0, uint32_t a1,
                                        uint32_t a2, uint32_t a3,
                                        uint32_t b0, uint32_t b1) {
    asm volatile(
        "mma.sync.aligned.m16n8k16.row.col.f32.f16.f16.f32 "
        "{%0,%1,%2,%3}, {%4,%5,%6,%7}, {%8,%9}, {%0,%1,%2,%3};"
        : "+f"(c[0]), "+f"(c[1]), "+f"(c[2]), "+f"(c[3])
        : "r"(a0), "r"(a1), "r"(a2), "r"(a3), "r"(b0), "r"(b1));
}

// ---------------------------------------------------------------------------
// fp16 GEMM mainloop: acc(64x32 per warp) for C = A @ W^T tile.
// A[M,1024], W[N,1024] row-major fp32. 256 threads = 8 warps (2x4).
// BK=16, double-buffered smem of half2 units: [128 rows][12 units]
// (8 data + 4 pad; stride 12 -> fragment LDS conflict-free: banks 12g+t all
// distinct across the warp). fp32 LDG -> __floats2half2_rn at STS.
// ---------------------------------------------------------------------------
#define PADH 12

__device__ __forceinline__ void gemm_mma_mainloop(
    const float* __restrict__ A, const float* __restrict__ W,
    int m0, int n0, float acc[4][4][4])
{
    __shared__ uint32_t As[2][128 * PADH];
    __shared__ uint32_t Ws[2][128 * PADH];

    const int tid  = threadIdx.x;
    const int lane = tid & 31, wid = tid >> 5;
    const int wm = wid & 1, wn = wid >> 1;
    const int g = lane >> 2, t = lane & 3;

    // Loader: thread handles rows (tid>>2) and +64, k-slot (tid&3)*4..+3
    const int lrow = tid >> 2, lc4 = tid & 3;
    const float4* Ag0 = (const float4*)A + (size_t)(m0 + lrow) * 256 + lc4;
    const float4* Ag1 = Ag0 + (size_t)64 * 256;
    const float4* Wg0 = (const float4*)W + (size_t)(n0 + lrow) * 256 + lc4;
    const float4* Wg1 = Wg0 + (size_t)64 * 256;
    const int uA0 = lrow * PADH + lc4 * 2;
    const int uA1 = (lrow + 64) * PADH + lc4 * 2;

#pragma unroll
    for (int mi = 0; mi < 4; mi++)
#pragma unroll
        for (int nj = 0; nj < 4; nj++)
#pragma unroll
            for (int e = 0; e < 4; e++) acc[mi][nj][e] = 0.f;

    float4 pa0 = Ag0[0], pa1 = Ag1[0], pw0 = Wg0[0], pw1 = Wg1[0];

    auto sts = [&](int s) {
        uint32_t* as = As[s];
        uint32_t* ws = Ws[s];
        as[uA0] = pk(pa0.x, pa0.y); as[uA0 + 1] = pk(pa0.z, pa0.w);
        as[uA1] = pk(pa1.x, pa1.y); as[uA1 + 1] = pk(pa1.z, pa1.w);
        ws[uA0] = pk(pw0.x, pw0.y); ws[uA0 + 1] = pk(pw0.z, pw0.w);
        ws[uA1] = pk(pw1.x, pw1.y); ws[uA1 + 1] = pk(pw1.z, pw1.w);
    };

    sts(0);
    __syncthreads();

    const int ra = wm * 64 + g;
    const int cb = wn * 32 + g;

    for (int ch = 0; ch < 64; ch++) {
        const int s = ch & 1;
        if (ch < 63) {
            const size_t ko = (size_t)(ch + 1) * 4;
            pa0 = Ag0[ko]; pa1 = Ag1[ko];
            pw0 = Wg0[ko]; pw1 = Wg1[ko];
        }
        const uint32_t* as = As[s];
        const uint32_t* ws = Ws[s];
        uint32_t af[4][4], bf[4][2];
#pragma unroll
        for (int mi = 0; mi < 4; mi++) {
            const int r = (ra + mi * 16) * PADH;
            af[mi][0] = as[r + t];
            af[mi][1] = as[r + 8 * PADH + t];
            af[mi][2] = as[r + t + 4];
            af[mi][3] = as[r + 8 * PADH + t + 4];
        }
#pragma unroll
        for (int nj = 0; nj < 4; nj++) {
            const int c = (cb + nj * 8) * PADH;
            bf[nj][0] = ws[c + t];
            bf[nj][1] = ws[c + t + 4];
        }
#pragma unroll
        for (int mi = 0; mi < 4; mi++)
#pragma unroll
            for (int nj = 0; nj < 4; nj++)
                mma_f16(acc[mi][nj], af[mi][0], af[mi][1], af[mi][2], af[mi][3],
                        bf[nj][0], bf[nj][1]);
        if (ch < 63) {
            sts(s ^ 1);
            __syncthreads();
        }
    }
}

// ---------------------------------------------------------------------------
// Fused QKV projection. z: 0=Q (scaled, [B,H,T,hd]), 1=K natural, 2=V transposed
// ---------------------------------------------------------------------------
__global__ void __launch_bounds__(256) qkv_mma_kernel(
    const float* __restrict__ x, const float* __restrict__ wq,
    const float* __restrict__ wk, const float* __restrict__ wv)
{
    const int z = blockIdx.z;
    const float* W = (z == 0) ? wq : (z == 1) ? wk : wv;
    const int m0 = blockIdx.y * 128, n0 = blockIdx.x * 128;

    float acc[4][4][4];
    gemm_mma_mainloop(x, W, m0, n0, acc);

    const int tid = threadIdx.x;
    const int lane = tid & 31, wid = tid >> 5;
    const int wm = wid & 1, wn = wid >> 1;
    const int g = lane >> 2, t = lane & 3;

#pragma unroll
    for (int mi = 0; mi < 4; mi++) {
#pragma unroll
        for (int half = 0; half < 2; half++) {
            const int m = m0 + wm * 64 + mi * 16 + g + half * 8;
            const int bb = m >> 11, tt = m & 2047;
#pragma unroll
            for (int nj = 0; nj < 4; nj++) {
                const int n = n0 + wn * 32 + nj * 8 + t * 2;
                const int h = n >> 6, d = n & 63;
                float v0 = acc[mi][nj][half * 2 + 0];
                float v1 = acc[mi][nj][half * 2 + 1];
                if (z == 0) {
                    float2 v = make_float2(v0 * 0.125f, v1 * 0.125f);
                    *(float2*)&g_Q[((size_t)(bb * HN + h) * TSEQ + tt) * HDM + d] = v;
                } else if (z == 1) {
                    float2 v = make_float2(v0, v1);
                    *(float2*)&g_K[((size_t)(bb * HN + h) * TSEQ + tt) * HDM + d] = v;
                } else {
                    g_Vt[((size_t)(bb * HN + h) * HDM + d)     * TSEQ + tt] = v0;
                    g_Vt[((size_t)(bb * HN + h) * HDM + d + 1) * TSEQ + tt] = v1;
                }
            }
        }
    }
}

// ---------------------------------------------------------------------------
// Output projection: d_out = g_O @ wo^T
// ---------------------------------------------------------------------------
__global__ void __launch_bounds__(256) out_mma_kernel(
    const float* __restrict__ wo, float* __restrict__ out)
{
    const int m0 = blockIdx.y * 128, n0 = blockIdx.x * 128;

    float acc[4][4][4];
    gemm_mma_mainloop(g_O, wo, m0, n0, acc);

    const int tid = threadIdx.x;
    const int lane = tid & 31, wid = tid >> 5;
    const int wm = wid & 1, wn = wid >> 1;
    const int g = lane >> 2, t = lane & 3;

#pragma unroll
    for (int mi = 0; mi < 4; mi++) {
#pragma unroll
        for (int half = 0; half < 2; half++) {
            const int m = m0 + wm * 64 + mi * 16 + g + half * 8;
#pragma unroll
            for (int nj = 0; nj < 4; nj++) {
                const int n = n0 + wn * 32 + nj * 8 + t * 2;
                float2 v = make_float2(acc[mi][nj][half * 2 + 0],
                                       acc[mi][nj][half * 2 + 1]);
                *(float2*)&out[(size_t)m * DM + n] = v;
            }
        }
    }
}

// ---------------------------------------------------------------------------
// Causal flash attention on mma.sync fp16 (fp32 softmax + accumulators).
// BM=128 q-rows/CTA, BN=64 kv/iter, 8 warps x 16 rows (warp-local softmax).
// Smem half2 units, stride 36 (32 data + 4 pad -> banks 4g+t, conflict-free):
// Qs[128][36], Ks[64][36], Vt[64][36], Ps[128][36] = 55296 B dynamic.
// ---------------------------------------------------------------------------
#define FST 36
#define FLASH_SMEM (384 * FST * 4)

__global__ void __launch_bounds__(256) flash_mma_kernel()
{
    extern __shared__ uint32_t fsu[];
    uint32_t* Qs = fsu;                 // [128][FST]
    uint32_t* Ks = fsu + 128 * FST;     // [64][FST]
    uint32_t* Vt = Ks + 64 * FST;       // [64][FST]
    uint32_t* Ps = Vt + 64 * FST;       // [128][FST]

    const int tid = threadIdx.x, lane = tid & 31, w = tid >> 5;
    const int g = lane >> 2, t = lane & 3;
    const int qt = gridDim.x - 1 - blockIdx.x;   // heavy tiles first
    const int bh = blockIdx.y;
    const int q0 = qt * 128;
    const int rm = w * 16;

    const float* Qg = g_Q  + (size_t)bh * TSEQ * HDM + (size_t)q0 * HDM;
    const float* Kg = g_K  + (size_t)bh * TSEQ * HDM;
    const float* Vg = g_Vt + (size_t)bh * HDM * TSEQ;

    // Q tile -> fp16 smem
#pragma unroll
    for (int it = 0; it < 8; it++) {
        int u = tid + it * 256, r = u >> 4, c = u & 15;
        float4 v = *(const float4*)&Qg[(size_t)r * HDM + c * 4];
        Qs[r * FST + 2 * c]     = pk(v.x, v.y);
        Qs[r * FST + 2 * c + 1] = pk(v.z, v.w);
    }

    float mi[2] = {-INFINITY, -INFINITY}, li[2] = {0.f, 0.f};
    float accO[8][4];
#pragma unroll
    for (int nj = 0; nj < 8; nj++)
#pragma unroll
        for (int e = 0; e < 4; e++) accO[nj][e] = 0.f;

    const int n_kt = 2 * (qt + 1);
    for (int kt = 0; kt < n_kt; kt++) {
        __syncthreads();   // prior-iter K/V reads complete
#pragma unroll
        for (int it = 0; it < 4; it++) {
            int u = tid + it * 256, r = u >> 4, c = u & 15;
            float4 kv = *(const float4*)&Kg[(size_t)(kt * 64 + r) * HDM + c * 4];
            Ks[r * FST + 2 * c]     = pk(kv.x, kv.y);
            Ks[r * FST + 2 * c + 1] = pk(kv.z, kv.w);
            float4 vv = *(const float4*)&Vg[(size_t)r * TSEQ + kt * 64 + c * 4];
            Vt[r * FST + 2 * c]     = pk(vv.x, vv.y);
            Vt[r * FST + 2 * c + 1] = pk(vv.z, vv.w);
        }
        __syncthreads();

        // S = Q @ K^T  (Q pre-scaled); k=64 -> 4 MMA steps
        float s[8][4];
#pragma unroll
        for (int nj = 0; nj < 8; nj++)
#pragma unroll
            for (int e = 0; e < 4; e++) s[nj][e] = 0.f;
#pragma unroll
        for (int ks = 0; ks < 4; ks++) {
            const int kk = ks * 8;
            uint32_t a0 = Qs[(rm + g) * FST + kk + t];
            uint32_t a1 = Qs[(rm + g + 8) * FST + kk + t];
            uint32_t a2 = Qs[(rm + g) * FST + kk + t + 4];
            uint32_t a3 = Qs[(rm + g + 8) * FST + kk + t + 4];
#pragma unroll
            for (int nj = 0; nj < 8; nj++) {
                uint32_t b0 = Ks[(nj * 8 + g) * FST + kk + t];
                uint32_t b1 = Ks[(nj * 8 + g) * FST + kk + t + 4];
                mma_f16(s[nj], a0, a1, a2, a3, b0, b1);
            }
        }

        if (kt >= 2 * qt) {  // causal mask (only the two diagonal-band tiles)
            const int r0 = q0 + rm + g, r1 = r0 + 8;
#pragma unroll
            for (int nj = 0; nj < 8; nj++) {
                const int col = kt * 64 + nj * 8 + 2 * t;
                if (col     > r0) s[nj][0] = -INFINITY;
                if (col + 1 > r0) s[nj][1] = -INFINITY;
                if (col     > r1) s[nj][2] = -INFINITY;
                if (col + 1 > r1) s[nj][3] = -INFINITY;
            }
        }

        // Online softmax per row-half; P -> fp16 smem (same-warp rows only)
#pragma unroll
        for (int h = 0; h < 2; h++) {
            float vm = -INFINITY;
#pragma unroll
            for (int nj = 0; nj < 8; nj++)
                vm = fmaxf(vm, fmaxf(s[nj][2 * h], s[nj][2 * h + 1]));
            vm = fmaxf(vm, __shfl_xor_sync(0xffffffffu, vm, 1));
            vm = fmaxf(vm, __shfl_xor_sync(0xffffffffu, vm, 2));
            const float mnew = fmaxf(mi[h], vm);
            const float alpha = __expf(mi[h] - mnew);
            float rs = 0.f;
            const int prow = (rm + g + 8 * h) * FST;
#pragma unroll
            for (int nj = 0; nj < 8; nj++) {
                float p0 = __expf(s[nj][2 * h]     - mnew);
                float p1 = __expf(s[nj][2 * h + 1] - mnew);
                rs += p0 + p1;
                Ps[prow + nj * 4 + t] = pk(p0, p1);
            }
            rs += __shfl_xor_sync(0xffffffffu, rs, 1);
            rs += __shfl_xor_sync(0xffffffffu, rs, 2);
            li[h] = li[h] * alpha + rs;
            mi[h] = mnew;
#pragma unroll
            for (int nj = 0; nj < 8; nj++) {
                accO[nj][2 * h]     *= alpha;
                accO[nj][2 * h + 1] *= alpha;
            }
        }
        __syncwarp();

        // O += P @ V   (B operand = transposed V: Vt[d][token])
#pragma unroll
        for (int ks = 0; ks < 4; ks++) {
            const int kk = ks * 8;
            uint32_t a0 = Ps[(rm + g) * FST + kk + t];
            uint32_t a1 = Ps[(rm + g + 8) * FST + kk + t];
            uint32_t a2 = Ps[(rm + g) * FST + kk + t + 4];
            uint32_t a3 = Ps[(rm + g + 8) * FST + kk + t + 4];
#pragma unroll
            for (int nj = 0; nj < 8; nj++) {
                uint32_t b0 = Vt[(nj * 8 + g) * FST + kk + t];
                uint32_t b1 = Vt[(nj * 8 + g) * FST + kk + t + 4];
                mma_f16(accO[nj], a0, a1, a2, a3, b0, b1);
            }
        }
    }

    // Epilogue: O / l into merged-head layout [B*T, D]
    const int b = bh >> 4, hh = bh & 15;
    const float inv0 = 1.f / li[0], inv1 = 1.f / li[1];
    const int r0 = q0 + rm + g;
#pragma unroll
    for (int nj = 0; nj < 8; nj++) {
        const int col = hh * 64 + nj * 8 + 2 * t;
        *(float2*)&g_O[(size_t)(b * TSEQ + r0) * DM + col] =
            make_float2(accO[nj][0] * inv0, accO[nj][1] * inv0);
        *(float2*)&g_O[(size_t)(b * TSEQ + r0 + 8) * DM + col] =
            make_float2(accO[nj][2] * inv1, accO[nj][3] * inv1);
    }
}

// ---------------------------------------------------------------------------
extern "C" void kernel_launch(void* const* d_in, const int* in_sizes, int n_in,
                              void* d_out, int out_size)
{
    const float* x  = (const float*)d_in[0];
    const float* wq = (const float*)d_in[1];
    const float* wk = (const float*)d_in[2];
    const float* wv = (const float*)d_in[3];
    const float* wo = (const float*)d_in[4];

    cudaFuncSetAttribute(flash_mma_kernel,
                         cudaFuncAttributeMaxDynamicSharedMemorySize, FLASH_SMEM);

    qkv_mma_kernel<<<dim3(DM / 128, MTOT / 128, 3), 256>>>(x, wq, wk, wv);
    flash_mma_kernel<<<dim3(TSEQ / 128, BSZ * HN), 256, FLASH_SMEM>>>();
    out_mma_kernel<<<dim3(DM / 128, MTOT / 128), 256>>>(wo, (float*)d_out);
}

// round 9
// speedup vs baseline: 5.2817x; 1.2859x over previous
#include <cuda_runtime.h>
#include <cuda_fp16.h>
#include <math.h>
#include <cstdint>

// Problem constants
#define BSZ 2
#define TSEQ 2048
#define DM   1024
#define HN   16
#define HDM  64
#define MTOT (BSZ*TSEQ)   // 4096

// Scratch (allocation-free rule: __device__ globals)
__device__ __half g_x16 [MTOT*DM];        // fp16 copy of x
__device__ __half g_wq16[DM*DM];
__device__ __half g_wk16[DM*DM];
__device__ __half g_wv16[DM*DM];
__device__ __half g_wo16[DM*DM];
__device__ __half g_Q16 [BSZ*HN*TSEQ*HDM];  // [B,H,T,hd], pre-scaled 1/8
__device__ __half g_K16 [BSZ*HN*TSEQ*HDM];  // [B,H,T,hd]
__device__ __half g_Vt16[BSZ*HN*HDM*TSEQ];  // [B,H,hd,T]
__device__ __half g_O16 [MTOT*DM];          // [B*T, D] attention output

// ---------------------------------------------------------------------------
// helpers
// ---------------------------------------------------------------------------
__device__ __forceinline__ uint32_t pk(float lo, float hi) {
    __half2 h = __floats2half2_rn(lo, hi);
    return *(uint32_t*)&h;
}
__device__ __forceinline__ uint32_t smem_u32(const void* p) {
    uint32_t a;
    asm("{ .reg .u64 t; cvta.to.shared.u64 t, %1; cvt.u32.u64 %0, t; }"
        : "=r"(a) : "l"(p));
    return a;
}
__device__ __forceinline__ void cpa16(uint32_t dst, const void* src) {
    asm volatile("cp.async.cg.shared.global [%0], [%1], 16;"
                 :: "r"(dst), "l"(src) : "memory");
}
#define CP_COMMIT() asm volatile("cp.async.commit_group;" ::: "memory")
#define CP_WAIT(n)  asm volatile("cp.async.wait_group %0;" :: "n"(n) : "memory")

// mma.sync m16n8k16 fp16 inputs, fp32 accum.
__device__ __forceinline__ void mma_f16(float c[4], uint32_t a0, uint32_t a1,
                                        uint32_t a2, uint32_t a3,
                                        uint32_t b0, uint32_t b1) {
    asm volatile(
        "mma.sync.aligned.m16n8k16.row.col.f32.f16.f16.f32 "
        "{%0,%1,%2,%3}, {%4,%5,%6,%7}, {%8,%9}, {%0,%1,%2,%3};"
        : "+f"(c[0]), "+f"(c[1]), "+f"(c[2]), "+f"(c[3])
        : "r"(a0), "r"(a1), "r"(a2), "r"(a3), "r"(b0), "r"(b1));
}

// ---------------------------------------------------------------------------
// Prepass: fp32 -> fp16 for x and the four weights. float4-granular.
// ---------------------------------------------------------------------------
#define NX4 (MTOT*DM/4)     // 1048576
#define NW4 (DM*DM/4)       // 262144
#define NCVT (NX4 + 4*NW4)  // 2097152

__global__ void __launch_bounds__(256) cvt16_kernel(
    const float* __restrict__ x, const float* __restrict__ wq,
    const float* __restrict__ wk, const float* __restrict__ wv,
    const float* __restrict__ wo)
{
    int i = blockIdx.x * 256 + threadIdx.x;
    if (i >= NCVT) return;
    const float4* src; __half* dst; int j;
    if (i < NX4)            { src = (const float4*)x;  dst = g_x16;  j = i; }
    else if (i < NX4+NW4)   { src = (const float4*)wq; dst = g_wq16; j = i - NX4; }
    else if (i < NX4+2*NW4) { src = (const float4*)wk; dst = g_wk16; j = i - NX4 - NW4; }
    else if (i < NX4+3*NW4) { src = (const float4*)wv; dst = g_wv16; j = i - NX4 - 2*NW4; }
    else                    { src = (const float4*)wo; dst = g_wo16; j = i - NX4 - 3*NW4; }
    float4 v = src[j];
    uint32_t* d = (uint32_t*)(dst + (size_t)j * 4);
    d[0] = pk(v.x, v.y);
    d[1] = pk(v.z, v.w);
}

// ---------------------------------------------------------------------------
// fp16 GEMM mainloop: C(128x128) = A @ W^T, A/W fp16 row-major [.,1024].
// 256 threads = 8 warps (2x4), each warp 64x32. BK=32, 4 smem stages,
// cp.async with 3 groups in flight; ONE __syncthreads per chunk (group ch+3
// targets the stage freed at chunk ch-1, protected by the top barrier).
// Row stride 20 uint32 (16 data + 4 pad): fragment LDS banks 20g+t distinct.
// ---------------------------------------------------------------------------
#define GST 20
#define GEMM_SMEM (8 * 128 * GST * 4)   // 4 stages x (A+W) = 81920 B

__device__ __forceinline__ void gemm16_mainloop(
    const __half* __restrict__ A, const __half* __restrict__ W,
    int m0, int n0, uint32_t* gsm, float acc[4][4][4])
{
    const int tid = threadIdx.x, lane = tid & 31, wid = tid >> 5;
    const int wm = wid & 1, wn = wid >> 1;
    const int g = lane >> 2, t = lane & 3;
    const int r = tid >> 1, h2 = tid & 1;

    const uint32_t sbase = smem_u32(gsm);
    const __half* ga = A + (size_t)(m0 + r) * 1024 + h2 * 16;
    const __half* gw = W + (size_t)(n0 + r) * 1024 + h2 * 16;
    const uint32_t du = (uint32_t)(r * GST + h2 * 8) * 4;

#pragma unroll
    for (int mi = 0; mi < 4; mi++)
#pragma unroll
        for (int nj = 0; nj < 4; nj++)
#pragma unroll
            for (int e = 0; e < 4; e++) acc[mi][nj][e] = 0.f;

    auto issue = [&](int ch, int st) {
        const uint32_t so = (uint32_t)st * (128 * GST * 4);
        uint32_t da = sbase + so + du;
        uint32_t dw = sbase + 4 * 128 * GST * 4 + so + du;
        const __half* a = ga + ch * 32;
        const __half* w = gw + ch * 32;
        cpa16(da, a);      cpa16(da + 16, a + 8);
        cpa16(dw, w);      cpa16(dw + 16, w + 8);
    };

    issue(0, 0); CP_COMMIT();
    issue(1, 1); CP_COMMIT();
    issue(2, 2); CP_COMMIT();

    const int ra = wm * 64 + g;
    const int cb = wn * 32 + g;

    for (int ch = 0; ch < 32; ch++) {
        const int st = ch & 3;
        CP_WAIT(2);
        __syncthreads();
        const uint32_t* as = gsm + st * 128 * GST;
        const uint32_t* ws = gsm + 4 * 128 * GST + st * 128 * GST;
#pragma unroll
        for (int kq = 0; kq < 2; kq++) {
            const int kk = kq * 8;
            uint32_t af[4][4], bf[4][2];
#pragma unroll
            for (int mi = 0; mi < 4; mi++) {
                const int rr = (ra + mi * 16) * GST;
                af[mi][0] = as[rr + kk + t];
                af[mi][1] = as[rr + 8 * GST + kk + t];
                af[mi][2] = as[rr + kk + t + 4];
                af[mi][3] = as[rr + 8 * GST + kk + t + 4];
            }
#pragma unroll
            for (int nj = 0; nj < 4; nj++) {
                const int cc = (cb + nj * 8) * GST;
                bf[nj][0] = ws[cc + kk + t];
                bf[nj][1] = ws[cc + kk + t + 4];
            }
#pragma unroll
            for (int mi = 0; mi < 4; mi++)
#pragma unroll
                for (int nj = 0; nj < 4; nj++)
                    mma_f16(acc[mi][nj], af[mi][0], af[mi][1], af[mi][2], af[mi][3],
                            bf[nj][0], bf[nj][1]);
        }
        if (ch + 3 < 32) issue(ch + 3, (ch + 3) & 3);
        CP_COMMIT();   // always commit (possibly empty) -> uniform group count
    }
}

// ---------------------------------------------------------------------------
// Fused QKV projection. z: 0=Q (scaled), 1=K natural, 2=V transposed. fp16 out.
// ---------------------------------------------------------------------------
__global__ void __launch_bounds__(256) qkv_mma_kernel()
{
    extern __shared__ uint32_t gsm[];
    const int z = blockIdx.z;
    const __half* W = (z == 0) ? g_wq16 : (z == 1) ? g_wk16 : g_wv16;
    const int m0 = blockIdx.y * 128, n0 = blockIdx.x * 128;

    float acc[4][4][4];
    gemm16_mainloop(g_x16, W, m0, n0, gsm, acc);

    const int tid = threadIdx.x;
    const int lane = tid & 31, wid = tid >> 5;
    const int wm = wid & 1, wn = wid >> 1;
    const int g = lane >> 2, t = lane & 3;

#pragma unroll
    for (int mi = 0; mi < 4; mi++) {
#pragma unroll
        for (int half = 0; half < 2; half++) {
            const int m = m0 + wm * 64 + mi * 16 + g + half * 8;
            const int bb = m >> 11, tt = m & 2047;
#pragma unroll
            for (int nj = 0; nj < 4; nj++) {
                const int n = n0 + wn * 32 + nj * 8 + t * 2;
                const int h = n >> 6, d = n & 63;
                float v0 = acc[mi][nj][half * 2 + 0];
                float v1 = acc[mi][nj][half * 2 + 1];
                if (z == 0) {
                    *(uint32_t*)&g_Q16[((size_t)(bb * HN + h) * TSEQ + tt) * HDM + d] =
                        pk(v0 * 0.125f, v1 * 0.125f);
                } else if (z == 1) {
                    *(uint32_t*)&g_K16[((size_t)(bb * HN + h) * TSEQ + tt) * HDM + d] =
                        pk(v0, v1);
                } else {
                    g_Vt16[((size_t)(bb * HN + h) * HDM + d)     * TSEQ + tt] = __float2half(v0);
                    g_Vt16[((size_t)(bb * HN + h) * HDM + d + 1) * TSEQ + tt] = __float2half(v1);
                }
            }
        }
    }
}

// ---------------------------------------------------------------------------
// Output projection: d_out = g_O16 @ wo^T (fp32 out)
// ---------------------------------------------------------------------------
__global__ void __launch_bounds__(256) out_mma_kernel(float* __restrict__ out)
{
    extern __shared__ uint32_t gsm[];
    const int m0 = blockIdx.y * 128, n0 = blockIdx.x * 128;

    float acc[4][4][4];
    gemm16_mainloop(g_O16, g_wo16, m0, n0, gsm, acc);

    const int tid = threadIdx.x;
    const int lane = tid & 31, wid = tid >> 5;
    const int wm = wid & 1, wn = wid >> 1;
    const int g = lane >> 2, t = lane & 3;

#pragma unroll
    for (int mi = 0; mi < 4; mi++) {
#pragma unroll
        for (int half = 0; half < 2; half++) {
            const int m = m0 + wm * 64 + mi * 16 + g + half * 8;
#pragma unroll
            for (int nj = 0; nj < 4; nj++) {
                const int n = n0 + wn * 32 + nj * 8 + t * 2;
                float2 v = make_float2(acc[mi][nj][half * 2 + 0],
                                       acc[mi][nj][half * 2 + 1]);
                *(float2*)&out[(size_t)m * DM + n] = v;
            }
        }
    }
}

// ---------------------------------------------------------------------------
// Causal flash attention, fp16 mma + fp32 softmax/accum, cp.async K/V prefetch.
// BM=128, BN=64, 8 warps x 16 rows. K/V 3-stage; one __syncthreads per kt.
// Smem (uint32 units, row stride FST=36): Q 128, K 3x64, V 3x64, P 128 rows.
// ---------------------------------------------------------------------------
#define FST 36
#define FLASH_SMEM ((128*FST + 3*64*FST*2 + 128*FST) * 4)   // 92160 B

__global__ void __launch_bounds__(256) flash_mma_kernel()
{
    extern __shared__ uint32_t fsu[];
    uint32_t* Qs = fsu;                       // [128][FST]
    uint32_t* Ksb = fsu + 128 * FST;          // 3 x [64][FST]
    uint32_t* Vtb = Ksb + 3 * 64 * FST;       // 3 x [64][FST]
    uint32_t* Ps = Vtb + 3 * 64 * FST;        // [128][FST]
    const uint32_t sbase = smem_u32(fsu);

    const int tid = threadIdx.x, lane = tid & 31, w = tid >> 5;
    const int g = lane >> 2, t = lane & 3;
    const int qt = gridDim.x - 1 - blockIdx.x;
    const int bh = blockIdx.y;
    const int q0 = qt * 128;
    const int rm = w * 16;

    const __half* Qg = g_Q16  + (size_t)bh * TSEQ * HDM + (size_t)q0 * HDM;
    const __half* Kg = g_K16  + (size_t)bh * TSEQ * HDM;
    const __half* Vg = g_Vt16 + (size_t)bh * HDM * TSEQ;

    // Q tile via cp.async (group 0)
#pragma unroll
    for (int i = 0; i < 4; i++) {
        int u = tid + i * 256, rq = u >> 3, c = u & 7;
        cpa16(sbase + (uint32_t)(rq * FST + c * 4) * 4, Qg + (size_t)rq * HDM + c * 8);
    }
    CP_COMMIT();

    // K/V issue for stage st (chunks: 64 rows x 8 per matrix, 2 per thread)
    auto issueKV = [&](int kt, int st) {
        const uint32_t ko = (uint32_t)(128 * FST + st * 64 * FST) * 4;
        const uint32_t vo = (uint32_t)(128 * FST + (3 + st) * 64 * FST) * 4;
#pragma unroll
        for (int i = 0; i < 2; i++) {
            int u = tid + i * 256, rk = u >> 3, c = u & 7;
            cpa16(sbase + ko + (uint32_t)(rk * FST + c * 4) * 4,
                  Kg + (size_t)(kt * 64 + rk) * HDM + c * 8);
            cpa16(sbase + vo + (uint32_t)(rk * FST + c * 4) * 4,
                  Vg + (size_t)rk * TSEQ + kt * 64 + c * 8);
        }
    };

    const int n_kt = 2 * (qt + 1);
    issueKV(0, 0); CP_COMMIT();
    issueKV(1, 1); CP_COMMIT();

    float mi[2] = {-INFINITY, -INFINITY}, li[2] = {0.f, 0.f};
    float accO[8][4];
#pragma unroll
    for (int nj = 0; nj < 8; nj++)
#pragma unroll
        for (int e = 0; e < 4; e++) accO[nj][e] = 0.f;

    int st = 0;
    for (int kt = 0; kt < n_kt; kt++) {
        CP_WAIT(1);        // in-order groups: KV(kt) (and Q) complete
        __syncthreads();
        const uint32_t* Ks = Ksb + st * 64 * FST;
        const uint32_t* Vt = Vtb + st * 64 * FST;

        // S = Q @ K^T  (Q pre-scaled); k=64 -> 4 MMA k-steps
        float s[8][4];
#pragma unroll
        for (int nj = 0; nj < 8; nj++)
#pragma unroll
            for (int e = 0; e < 4; e++) s[nj][e] = 0.f;
#pragma unroll
        for (int ks = 0; ks < 4; ks++) {
            const int kk = ks * 8;
            uint32_t a0 = Qs[(rm + g) * FST + kk + t];
            uint32_t a1 = Qs[(rm + g + 8) * FST + kk + t];
            uint32_t a2 = Qs[(rm + g) * FST + kk + t + 4];
            uint32_t a3 = Qs[(rm + g + 8) * FST + kk + t + 4];
#pragma unroll
            for (int nj = 0; nj < 8; nj++) {
                uint32_t b0 = Ks[(nj * 8 + g) * FST + kk + t];
                uint32_t b1 = Ks[(nj * 8 + g) * FST + kk + t + 4];
                mma_f16(s[nj], a0, a1, a2, a3, b0, b1);
            }
        }

        if (kt >= 2 * qt) {  // causal mask on the two diagonal-band tiles
            const int r0 = q0 + rm + g, r1 = r0 + 8;
#pragma unroll
            for (int nj = 0; nj < 8; nj++) {
                const int col = kt * 64 + nj * 8 + 2 * t;
                if (col     > r0) s[nj][0] = -INFINITY;
                if (col + 1 > r0) s[nj][1] = -INFINITY;
                if (col     > r1) s[nj][2] = -INFINITY;
                if (col + 1 > r1) s[nj][3] = -INFINITY;
            }
        }

        // Online softmax per row-half; P -> fp16 smem (same-warp rows only)
#pragma unroll
        for (int h = 0; h < 2; h++) {
            float vm = -INFINITY;
#pragma unroll
            for (int nj = 0; nj < 8; nj++)
                vm = fmaxf(vm, fmaxf(s[nj][2 * h], s[nj][2 * h + 1]));
            vm = fmaxf(vm, __shfl_xor_sync(0xffffffffu, vm, 1));
            vm = fmaxf(vm, __shfl_xor_sync(0xffffffffu, vm, 2));
            const float mnew = fmaxf(mi[h], vm);
            const float alpha = __expf(mi[h] - mnew);
            float rs = 0.f;
            const int prow = (rm + g + 8 * h) * FST;
#pragma unroll
            for (int nj = 0; nj < 8; nj++) {
                float p0 = __expf(s[nj][2 * h]     - mnew);
                float p1 = __expf(s[nj][2 * h + 1] - mnew);
                rs += p0 + p1;
                Ps[prow + nj * 4 + t] = pk(p0, p1);
            }
            rs += __shfl_xor_sync(0xffffffffu, rs, 1);
            rs += __shfl_xor_sync(0xffffffffu, rs, 2);
            li[h] = li[h] * alpha + rs;
            mi[h] = mnew;
#pragma unroll
            for (int nj = 0; nj < 8; nj++) {
                accO[nj][2 * h]     *= alpha;
                accO[nj][2 * h + 1] *= alpha;
            }
        }
        __syncwarp();

        // O += P @ V
#pragma unroll
        for (int ks = 0; ks < 4; ks++) {
            const int kk = ks * 8;
            uint32_t a0 = Ps[(rm + g) * FST + kk + t];
            uint32_t a1 = Ps[(rm + g + 8) * FST + kk + t];
            uint32_t a2 = Ps[(rm + g) * FST + kk + t + 4];
            uint32_t a3 = Ps[(rm + g + 8) * FST + kk + t + 4];
#pragma unroll
            for (int nj = 0; nj < 8; nj++) {
                uint32_t b0 = Vt[(nj * 8 + g) * FST + kk + t];
                uint32_t b1 = Vt[(nj * 8 + g) * FST + kk + t + 4];
                mma_f16(accO[nj], a0, a1, a2, a3, b0, b1);
            }
        }

        // prefetch kt+2 into stage (kt+2)%3 = stage freed at kt-1 (safe: all
        // warps passed this iteration's top barrier)
        if (kt + 2 < n_kt) issueKV(kt + 2, (st + 2 >= 3) ? st - 1 : st + 2);
        CP_COMMIT();
        st = (st + 1 >= 3) ? 0 : st + 1;
    }

    // Epilogue: O / l -> fp16 merged-head layout [B*T, D]
    const int b = bh >> 4, hh = bh & 15;
    const float inv0 = 1.f / li[0], inv1 = 1.f / li[1];
    const int r0 = q0 + rm + g;
#pragma unroll
    for (int nj = 0; nj < 8; nj++) {
        const int col = hh * 64 + nj * 8 + 2 * t;
        *(uint32_t*)&g_O16[(size_t)(b * TSEQ + r0) * DM + col] =
            pk(accO[nj][0] * inv0, accO[nj][1] * inv0);
        *(uint32_t*)&g_O16[(size_t)(b * TSEQ + r0 + 8) * DM + col] =
            pk(accO[nj][2] * inv1, accO[nj][3] * inv1);
    }
}

// ---------------------------------------------------------------------------
extern "C" void kernel_launch(void* const* d_in, const int* in_sizes, int n_in,
                              void* d_out, int out_size)
{
    const float* x  = (const float*)d_in[0];
    const float* wq = (const float*)d_in[1];
    const float* wk = (const float*)d_in[2];
    const float* wv = (const float*)d_in[3];
    const float* wo = (const float*)d_in[4];

    cudaFuncSetAttribute(qkv_mma_kernel, cudaFuncAttributeMaxDynamicSharedMemorySize, GEMM_SMEM);
    cudaFuncSetAttribute(out_mma_kernel, cudaFuncAttributeMaxDynamicSharedMemorySize, GEMM_SMEM);
    cudaFuncSetAttribute(flash_mma_kernel, cudaFuncAttributeMaxDynamicSharedMemorySize, FLASH_SMEM);

    cvt16_kernel<<<(NCVT + 255) / 256, 256>>>(x, wq, wk, wv, wo);
    qkv_mma_kernel<<<dim3(DM / 128, MTOT / 128, 3), 256, GEMM_SMEM>>>();
    flash_mma_kernel<<<dim3(TSEQ / 128, BSZ * HN), 256, FLASH_SMEM>>>();
    out_mma_kernel<<<dim3(DM / 128, MTOT / 128), 256, GEMM_SMEM>>>((float*)d_out);
}

// round 10
// speedup vs baseline: 5.6759x; 1.0746x over previous
#include <cuda_runtime.h>
#include <cuda_fp16.h>
#include <math.h>
#include <cstdint>

// Problem constants
#define BSZ 2
#define TSEQ 2048
#define DM   1024
#define HN   16
#define HDM  64
#define MTOT (BSZ*TSEQ)   // 4096

// Scratch (allocation-free rule: __device__ globals)
__device__ __half g_x16 [MTOT*DM];
__device__ __half g_wq16[DM*DM];
__device__ __half g_wk16[DM*DM];
__device__ __half g_wv16[DM*DM];
__device__ __half g_wo16[DM*DM];
__device__ __half g_Q16 [BSZ*HN*TSEQ*HDM];  // [B,H,T,hd], pre-scaled 1/8
__device__ __half g_K16 [BSZ*HN*TSEQ*HDM];  // [B,H,T,hd]
__device__ __half g_Vt16[BSZ*HN*HDM*TSEQ];  // [B,H,hd,T]
__device__ __half g_O16 [MTOT*DM];          // [B*T, D]

// ---------------------------------------------------------------------------
// helpers
// ---------------------------------------------------------------------------
__device__ __forceinline__ uint32_t pk(float lo, float hi) {
    __half2 h = __floats2half2_rn(lo, hi);
    return *(uint32_t*)&h;
}
__device__ __forceinline__ uint32_t smem_u32(const void* p) {
    uint32_t a;
    asm("{ .reg .u64 t; cvta.to.shared.u64 t, %1; cvt.u32.u64 %0, t; }"
        : "=r"(a) : "l"(p));
    return a;
}
__device__ __forceinline__ void cpa16(uint32_t dst, const void* src) {
    asm volatile("cp.async.cg.shared.global [%0], [%1], 16;"
                 :: "r"(dst), "l"(src) : "memory");
}
#define CP_COMMIT() asm volatile("cp.async.commit_group;" ::: "memory")
#define CP_WAIT(n)  asm volatile("cp.async.wait_group %0;" :: "n"(n) : "memory")

// ldmatrix x4: 4 8x8 b16 matrices; lane l of group (l>>3) supplies row addrs.
__device__ __forceinline__ void ldsm4(uint32_t f[4], uint32_t addr) {
    asm volatile("ldmatrix.sync.aligned.m8n8.x4.shared.b16 {%0,%1,%2,%3}, [%4];"
                 : "=r"(f[0]), "=r"(f[1]), "=r"(f[2]), "=r"(f[3]) : "r"(addr));
}

__device__ __forceinline__ void mma_f16(float c[4], uint32_t a0, uint32_t a1,
                                        uint32_t a2, uint32_t a3,
                                        uint32_t b0, uint32_t b1) {
    asm volatile(
        "mma.sync.aligned.m16n8k16.row.col.f32.f16.f16.f32 "
        "{%0,%1,%2,%3}, {%4,%5,%6,%7}, {%8,%9}, {%0,%1,%2,%3};"
        : "+f"(c[0]), "+f"(c[1]), "+f"(c[2]), "+f"(c[3])
        : "r"(a0), "r"(a1), "r"(a2), "r"(a3), "r"(b0), "r"(b1));
}

// ---------------------------------------------------------------------------
// Prepass: fp32 -> fp16 for x and the four weights.
// ---------------------------------------------------------------------------
#define NX4 (MTOT*DM/4)
#define NW4 (DM*DM/4)
#define NCVT (NX4 + 4*NW4)

__global__ void __launch_bounds__(256) cvt16_kernel(
    const float* __restrict__ x, const float* __restrict__ wq,
    const float* __restrict__ wk, const float* __restrict__ wv,
    const float* __restrict__ wo)
{
    int i = blockIdx.x * 256 + threadIdx.x;
    if (i >= NCVT) return;
    const float4* src; __half* dst; int j;
    if (i < NX4)            { src = (const float4*)x;  dst = g_x16;  j = i; }
    else if (i < NX4+NW4)   { src = (const float4*)wq; dst = g_wq16; j = i - NX4; }
    else if (i < NX4+2*NW4) { src = (const float4*)wk; dst = g_wk16; j = i - NX4 - NW4; }
    else if (i < NX4+3*NW4) { src = (const float4*)wv; dst = g_wv16; j = i - NX4 - 2*NW4; }
    else                    { src = (const float4*)wo; dst = g_wo16; j = i - NX4 - 3*NW4; }
    float4 v = src[j];
    uint32_t* d = (uint32_t*)(dst + (size_t)j * 4);
    d[0] = pk(v.x, v.y);
    d[1] = pk(v.z, v.w);
}

// ---------------------------------------------------------------------------
// fp16 GEMM mainloop: C(128x128) = A @ W^T. BK=32, 4 stages, cp.async,
// one __syncthreads per chunk. Fragment loads via ldmatrix.x4 (conflict-free
// with row stride 20 uint32: 8-row starts hit banks {0,20,8,28,16,4,24,12}).
// ---------------------------------------------------------------------------
#define GST 20
#define GEMM_SMEM (8 * 128 * GST * 4)   // 81920 B

__device__ __forceinline__ void gemm16_mainloop(
    const __half* __restrict__ A, const __half* __restrict__ W,
    int m0, int n0, uint32_t* gsm, float acc[4][4][4])
{
    const int tid = threadIdx.x, lane = tid & 31, wid = tid >> 5;
    const int wm = wid & 1, wn = wid >> 1;
    const int r = tid >> 1, h2 = tid & 1;

    const uint32_t sbase = smem_u32(gsm);
    const __half* ga = A + (size_t)(m0 + r) * 1024 + h2 * 16;
    const __half* gw = W + (size_t)(n0 + r) * 1024 + h2 * 16;
    const uint32_t du = (uint32_t)(r * GST + h2 * 8) * 4;

    // ldmatrix per-lane offsets (A: groups = row-half then k-half; B: k-half
    // then n-row-half so one x4 yields b0,b1 for nj and nj+1)
    const int arow = (lane & 7) + ((lane >> 3) & 1) * 8;
    const int acol = (lane >> 4) * 4;
    const int brow = (lane & 7) + ((lane >> 4) & 1) * 8;
    const int bcol = ((lane >> 3) & 1) * 4;
    const uint32_t aoff = (uint32_t)((wm * 64 + arow) * GST + acol) * 4;
    const uint32_t boff = (uint32_t)((wn * 32 + brow) * GST + bcol) * 4;
    const uint32_t wbase = sbase + 4 * 128 * GST * 4;

#pragma unroll
    for (int mi = 0; mi < 4; mi++)
#pragma unroll
        for (int nj = 0; nj < 4; nj++)
#pragma unroll
            for (int e = 0; e < 4; e++) acc[mi][nj][e] = 0.f;

    auto issue = [&](int ch, int st) {
        const uint32_t so = (uint32_t)st * (128 * GST * 4);
        uint32_t da = sbase + so + du;
        uint32_t dw = wbase + so + du;
        const __half* a = ga + ch * 32;
        const __half* w = gw + ch * 32;
        cpa16(da, a);      cpa16(da + 16, a + 8);
        cpa16(dw, w);      cpa16(dw + 16, w + 8);
    };

    issue(0, 0); CP_COMMIT();
    issue(1, 1); CP_COMMIT();
    issue(2, 2); CP_COMMIT();

    for (int ch = 0; ch < 32; ch++) {
        const int st = ch & 3;
        CP_WAIT(2);
        __syncthreads();
        const uint32_t so = (uint32_t)st * (128 * GST * 4);
        const uint32_t aa = sbase + so + aoff;
        const uint32_t bb = wbase + so + boff;
#pragma unroll
        for (int kq = 0; kq < 2; kq++) {
            const uint32_t kk4 = (uint32_t)(kq * 8) * 4;
            uint32_t af[4][4], bq[2][4];
#pragma unroll
            for (int mi = 0; mi < 4; mi++)
                ldsm4(af[mi], aa + (uint32_t)(mi * 16 * GST) * 4 + kk4);
#pragma unroll
            for (int p = 0; p < 2; p++)
                ldsm4(bq[p], bb + (uint32_t)(p * 16 * GST) * 4 + kk4);
#pragma unroll
            for (int mi = 0; mi < 4; mi++)
#pragma unroll
                for (int p = 0; p < 2; p++) {
                    mma_f16(acc[mi][2*p],   af[mi][0], af[mi][1], af[mi][2], af[mi][3],
                            bq[p][0], bq[p][1]);
                    mma_f16(acc[mi][2*p+1], af[mi][0], af[mi][1], af[mi][2], af[mi][3],
                            bq[p][2], bq[p][3]);
                }
        }
        if (ch + 3 < 32) issue(ch + 3, (ch + 3) & 3);
        CP_COMMIT();
    }
}

// ---------------------------------------------------------------------------
// Fused QKV projection. z: 0=Q (scaled), 1=K natural, 2=V transposed. fp16 out.
// ---------------------------------------------------------------------------
__global__ void __launch_bounds__(256) qkv_mma_kernel()
{
    extern __shared__ uint32_t gsm[];
    const int z = blockIdx.z;
    const __half* W = (z == 0) ? g_wq16 : (z == 1) ? g_wk16 : g_wv16;
    const int m0 = blockIdx.y * 128, n0 = blockIdx.x * 128;

    float acc[4][4][4];
    gemm16_mainloop(g_x16, W, m0, n0, gsm, acc);

    const int tid = threadIdx.x;
    const int lane = tid & 31, wid = tid >> 5;
    const int wm = wid & 1, wn = wid >> 1;
    const int g = lane >> 2, t = lane & 3;

#pragma unroll
    for (int mi = 0; mi < 4; mi++) {
#pragma unroll
        for (int half = 0; half < 2; half++) {
            const int m = m0 + wm * 64 + mi * 16 + g + half * 8;
            const int bb = m >> 11, tt = m & 2047;
#pragma unroll
            for (int nj = 0; nj < 4; nj++) {
                const int n = n0 + wn * 32 + nj * 8 + t * 2;
                const int h = n >> 6, d = n & 63;
                float v0 = acc[mi][nj][half * 2 + 0];
                float v1 = acc[mi][nj][half * 2 + 1];
                if (z == 0) {
                    *(uint32_t*)&g_Q16[((size_t)(bb * HN + h) * TSEQ + tt) * HDM + d] =
                        pk(v0 * 0.125f, v1 * 0.125f);
                } else if (z == 1) {
                    *(uint32_t*)&g_K16[((size_t)(bb * HN + h) * TSEQ + tt) * HDM + d] =
                        pk(v0, v1);
                } else {
                    g_Vt16[((size_t)(bb * HN + h) * HDM + d)     * TSEQ + tt] = __float2half(v0);
                    g_Vt16[((size_t)(bb * HN + h) * HDM + d + 1) * TSEQ + tt] = __float2half(v1);
                }
            }
        }
    }
}

// ---------------------------------------------------------------------------
// Output projection: d_out = g_O16 @ wo^T (fp32 out)
// ---------------------------------------------------------------------------
__global__ void __launch_bounds__(256) out_mma_kernel(float* __restrict__ out)
{
    extern __shared__ uint32_t gsm[];
    const int m0 = blockIdx.y * 128, n0 = blockIdx.x * 128;

    float acc[4][4][4];
    gemm16_mainloop(g_O16, g_wo16, m0, n0, gsm, acc);

    const int tid = threadIdx.x;
    const int lane = tid & 31, wid = tid >> 5;
    const int wm = wid & 1, wn = wid >> 1;
    const int g = lane >> 2, t = lane & 3;

#pragma unroll
    for (int mi = 0; mi < 4; mi++) {
#pragma unroll
        for (int half = 0; half < 2; half++) {
            const int m = m0 + wm * 64 + mi * 16 + g + half * 8;
#pragma unroll
            for (int nj = 0; nj < 4; nj++) {
                const int n = n0 + wn * 32 + nj * 8 + t * 2;
                float2 v = make_float2(acc[mi][nj][half * 2 + 0],
                                       acc[mi][nj][half * 2 + 1]);
                *(float2*)&out[(size_t)m * DM + n] = v;
            }
        }
    }
}

// ---------------------------------------------------------------------------
// Causal flash attention, fp16 mma + fp32 softmax/accum, cp.async K/V
// prefetch, ldmatrix fragment loads (stride 36 -> conflict-free).
// ---------------------------------------------------------------------------
#define FST 36
#define FLASH_SMEM ((128*FST + 3*64*FST*2 + 128*FST) * 4)   // 92160 B

__global__ void __launch_bounds__(256) flash_mma_kernel()
{
    extern __shared__ uint32_t fsu[];
    uint32_t* Ps = fsu + 128 * FST + 6 * 64 * FST;
    const uint32_t sbase = smem_u32(fsu);

    const int tid = threadIdx.x, lane = tid & 31, w = tid >> 5;
    const int g = lane >> 2, t = lane & 3;
    const int qt = gridDim.x - 1 - blockIdx.x;
    const int bh = blockIdx.y;
    const int q0 = qt * 128;
    const int rm = w * 16;

    const int arow = (lane & 7) + ((lane >> 3) & 1) * 8;
    const int acol = (lane >> 4) * 4;
    const int brow = (lane & 7) + ((lane >> 4) & 1) * 8;
    const int bcol = ((lane >> 3) & 1) * 4;
    const uint32_t qaddr = sbase + (uint32_t)((rm + arow) * FST + acol) * 4;
    const uint32_t paddr = qaddr + (uint32_t)(128 * FST + 6 * 64 * FST) * 4;
    const uint32_t kvoff = (uint32_t)(brow * FST + bcol) * 4;

    const __half* Qg = g_Q16  + (size_t)bh * TSEQ * HDM + (size_t)q0 * HDM;
    const __half* Kg = g_K16  + (size_t)bh * TSEQ * HDM;
    const __half* Vg = g_Vt16 + (size_t)bh * HDM * TSEQ;

    // Q tile via cp.async (group 0)
#pragma unroll
    for (int i = 0; i < 4; i++) {
        int u = tid + i * 256, rq = u >> 3, c = u & 7;
        cpa16(sbase + (uint32_t)(rq * FST + c * 4) * 4, Qg + (size_t)rq * HDM + c * 8);
    }
    CP_COMMIT();

    auto issueKV = [&](int kt, int st) {
        const uint32_t ko = (uint32_t)(128 * FST + st * 64 * FST) * 4;
        const uint32_t vo = (uint32_t)(128 * FST + (3 + st) * 64 * FST) * 4;
#pragma unroll
        for (int i = 0; i < 2; i++) {
            int u = tid + i * 256, rk = u >> 3, c = u & 7;
            cpa16(sbase + ko + (uint32_t)(rk * FST + c * 4) * 4,
                  Kg + (size_t)(kt * 64 + rk) * HDM + c * 8);
            cpa16(sbase + vo + (uint32_t)(rk * FST + c * 4) * 4,
                  Vg + (size_t)rk * TSEQ + kt * 64 + c * 8);
        }
    };

    const int n_kt = 2 * (qt + 1);
    issueKV(0, 0); CP_COMMIT();
    issueKV(1, 1); CP_COMMIT();

    float mi[2] = {-INFINITY, -INFINITY}, li[2] = {0.f, 0.f};
    float accO[8][4];
#pragma unroll
    for (int nj = 0; nj < 8; nj++)
#pragma unroll
        for (int e = 0; e < 4; e++) accO[nj][e] = 0.f;

    int st = 0;
    for (int kt = 0; kt < n_kt; kt++) {
        CP_WAIT(1);
        __syncthreads();
        const uint32_t kbase = sbase + (uint32_t)(128 * FST + st * 64 * FST) * 4 + kvoff;
        const uint32_t vbase = sbase + (uint32_t)(128 * FST + (3 + st) * 64 * FST) * 4 + kvoff;

        // S = Q @ K^T
        float s[8][4];
#pragma unroll
        for (int nj = 0; nj < 8; nj++)
#pragma unroll
            for (int e = 0; e < 4; e++) s[nj][e] = 0.f;
#pragma unroll
        for (int ks = 0; ks < 4; ks++) {
            const uint32_t kk4 = (uint32_t)(ks * 8) * 4;
            uint32_t aq[4];
            ldsm4(aq, qaddr + kk4);
#pragma unroll
            for (int p = 0; p < 4; p++) {
                uint32_t bq[4];
                ldsm4(bq, kbase + (uint32_t)(p * 16 * FST) * 4 + kk4);
                mma_f16(s[2*p],   aq[0], aq[1], aq[2], aq[3], bq[0], bq[1]);
                mma_f16(s[2*p+1], aq[0], aq[1], aq[2], aq[3], bq[2], bq[3]);
            }
        }

        if (kt >= 2 * qt) {  // causal mask on diagonal-band tiles
            const int r0 = q0 + rm + g, r1 = r0 + 8;
#pragma unroll
            for (int nj = 0; nj < 8; nj++) {
                const int col = kt * 64 + nj * 8 + 2 * t;
                if (col     > r0) s[nj][0] = -INFINITY;
                if (col + 1 > r0) s[nj][1] = -INFINITY;
                if (col     > r1) s[nj][2] = -INFINITY;
                if (col + 1 > r1) s[nj][3] = -INFINITY;
            }
        }

        // Online softmax per row-half; P -> fp16 smem (same-warp rows only)
#pragma unroll
        for (int h = 0; h < 2; h++) {
            float vm = -INFINITY;
#pragma unroll
            for (int nj = 0; nj < 8; nj++)
                vm = fmaxf(vm, fmaxf(s[nj][2 * h], s[nj][2 * h + 1]));
            vm = fmaxf(vm, __shfl_xor_sync(0xffffffffu, vm, 1));
            vm = fmaxf(vm, __shfl_xor_sync(0xffffffffu, vm, 2));
            const float mnew = fmaxf(mi[h], vm);
            const float alpha = __expf(mi[h] - mnew);
            float rs = 0.f;
            const int prow = (rm + g + 8 * h) * FST;
#pragma unroll
            for (int nj = 0; nj < 8; nj++) {
                float p0 = __expf(s[nj][2 * h]     - mnew);
                float p1 = __expf(s[nj][2 * h + 1] - mnew);
                rs += p0 + p1;
                Ps[prow + nj * 4 + t] = pk(p0, p1);
            }
            rs += __shfl_xor_sync(0xffffffffu, rs, 1);
            rs += __shfl_xor_sync(0xffffffffu, rs, 2);
            li[h] = li[h] * alpha + rs;
            mi[h] = mnew;
#pragma unroll
            for (int nj = 0; nj < 8; nj++) {
                accO[nj][2 * h]     *= alpha;
                accO[nj][2 * h + 1] *= alpha;
            }
        }
        __syncwarp();

        // O += P @ V
#pragma unroll
        for (int ks = 0; ks < 4; ks++) {
            const uint32_t kk4 = (uint32_t)(ks * 8) * 4;
            uint32_t ap[4];
            ldsm4(ap, paddr + kk4);
#pragma unroll
            for (int p = 0; p < 4; p++) {
                uint32_t bq[4];
                ldsm4(bq, vbase + (uint32_t)(p * 16 * FST) * 4 + kk4);
                mma_f16(accO[2*p],   ap[0], ap[1], ap[2], ap[3], bq[0], bq[1]);
                mma_f16(accO[2*p+1], ap[0], ap[1], ap[2], ap[3], bq[2], bq[3]);
            }
        }

        if (kt + 2 < n_kt) issueKV(kt + 2, (st + 2 >= 3) ? st - 1 : st + 2);
        CP_COMMIT();
        st = (st + 1 >= 3) ? 0 : st + 1;
    }

    // Epilogue: O / l -> fp16 merged-head layout [B*T, D]
    const int b = bh >> 4, hh = bh & 15;
    const float inv0 = 1.f / li[0], inv1 = 1.f / li[1];
    const int r0 = q0 + rm + g;
#pragma unroll
    for (int nj = 0; nj < 8; nj++) {
        const int col = hh * 64 + nj * 8 + 2 * t;
        *(uint32_t*)&g_O16[(size_t)(b * TSEQ + r0) * DM + col] =
            pk(accO[nj][0] * inv0, accO[nj][1] * inv0);
        *(uint32_t*)&g_O16[(size_t)(b * TSEQ + r0 + 8) * DM + col] =
            pk(accO[nj][2] * inv1, accO[nj][3] * inv1);
    }
}

// ---------------------------------------------------------------------------
extern "C" void kernel_launch(void* const* d_in, const int* in_sizes, int n_in,
                              void* d_out, int out_size)
{
    const float* x  = (const float*)d_in[0];
    const float* wq = (const float*)d_in[1];
    const float* wk = (const float*)d_in[2];
    const float* wv = (const float*)d_in[3];
    const float* wo = (const float*)d_in[4];

    cudaFuncSetAttribute(qkv_mma_kernel, cudaFuncAttributeMaxDynamicSharedMemorySize, GEMM_SMEM);
    cudaFuncSetAttribute(out_mma_kernel, cudaFuncAttributeMaxDynamicSharedMemorySize, GEMM_SMEM);
    cudaFuncSetAttribute(flash_mma_kernel, cudaFuncAttributeMaxDynamicSharedMemorySize, FLASH_SMEM);

    cvt16_kernel<<<(NCVT + 255) / 256, 256>>>(x, wq, wk, wv, wo);
    qkv_mma_kernel<<<dim3(DM / 128, MTOT / 128, 3), 256, GEMM_SMEM>>>();
    flash_mma_kernel<<<dim3(TSEQ / 128, BSZ * HN), 256, FLASH_SMEM>>>();
    out_mma_kernel<<<dim3(DM / 128, MTOT / 128), 256, GEMM_SMEM>>>((float*)d_out);
}